// round 4
// baseline (speedup 1.0000x reference)
#include <cuda_runtime.h>

#define BB   64
#define SS   4096
#define HH   256
#define FF   512      // 2*H
#define OUTD 24
#define NCHUNK 16     // s-chunks for context partials

// ---------------- scratch (static device globals; no allocs) ----------------
__device__ __align__(16) float g_qWh[BB*HH];      // hidden_q @ W_h + attn_b
__device__ __align__(16) float g_embT[BB*HH];     // gathered emb_temp
__device__ __align__(16) float g_scores[BB*SS];   // scores -> attn (in place)
__device__ __align__(16) float g_part[NCHUNK*BB*FF]; // context partial sums

// ---------------- helpers ----------------
__device__ __forceinline__ void cp_async16(void* sm, const void* g) {
    unsigned s = (unsigned)__cvta_generic_to_shared(sm);
    asm volatile("cp.async.cg.shared.global [%0], [%1], 16;" :: "r"(s), "l"(g));
}
#define CP_COMMIT() asm volatile("cp.async.commit_group;")
#define CP_WAIT0()  asm volatile("cp.async.wait_group 0;")

__device__ __forceinline__ unsigned long long dup_f32x2(float a) {
    unsigned long long r;
    unsigned ai = __float_as_uint(a);
    asm("mov.b64 %0, {%1, %1};" : "=l"(r) : "r"(ai));
    return r;
}
__device__ __forceinline__ void fma_f32x2(unsigned long long& acc,
                                          unsigned long long a,
                                          unsigned long long b) {
    asm("fma.rn.f32x2 %0, %1, %2, %0;" : "+l"(acc) : "l"(a), "l"(b));
}
__device__ __forceinline__ float2 unpack_f32x2(unsigned long long p) {
    unsigned lo, hi;
    asm("mov.b64 {%0, %1}, %2;" : "=r"(lo), "=r"(hi) : "l"(p));
    return make_float2(__uint_as_float(lo), __uint_as_float(hi));
}
__device__ __forceinline__ float sigmoidf_(float x) { return 1.0f / (1.0f + expf(-x)); }

// ---------------- kernel 1: gathers + qWh = emb_ctxt[idx] @ W_h + attn_b ----
__global__ void setup_kernel(const int* __restrict__ fc, const int* __restrict__ ft,
                             const float* __restrict__ emb_c, const float* __restrict__ emb_t,
                             const float* __restrict__ attn_W, const float* __restrict__ attn_b)
{
    __shared__ float q[HH];
    int b = blockIdx.x, tid = threadIdx.x;
    int ci = fc[b], ti = ft[b];
    q[tid] = emb_c[ci*HH + tid];
    g_embT[b*HH + tid] = emb_t[ti*HH + tid];
    __syncthreads();
    float acc = attn_b[tid];
#pragma unroll 8
    for (int k = 0; k < HH; k++) acc += q[k] * attn_W[k*HH + tid];
    g_qWh[b*HH + tid] = acc;
}

// ---------------- kernel 2: fused scores GEMM ----------------
// scores[b][s] = v . tanh( qWh[b] + E[b,s,:] @ W_e )
// CTA tile: 64 s-rows x 256 H-cols x K=512 (BK=16, double buffered).
// 256 threads = 16(tx: n) x 16(ty: m); thread tile 4m x 16n (8 f32x2 pairs).
__global__ void __launch_bounds__(256, 2)
scores_kernel(const float* __restrict__ E, const float* __restrict__ attn_W,
              const float* __restrict__ v)
{
    __shared__ float As[2][16][65];    // [k][m] (+pad) transposed E tile
    __shared__ float Bs[2][16][256];   // [k][n] W_e tile

    const int b  = blockIdx.y;
    const int s0 = blockIdx.x * 64;
    const int tid = threadIdx.x;
    const int tx = tid & 15, ty = tid >> 4;

    const float* We = attn_W + HH*HH;  // W_e = attn_W rows [256, 768)

    // A load indices: each thread one float4 per tile
    const int am = tid >> 2, aq = tid & 3;
    const float* Arow = E + (long)(b*SS + s0 + am) * FF;

    unsigned long long acc[4][8];
#pragma unroll
    for (int j = 0; j < 4; j++)
#pragma unroll
        for (int jj = 0; jj < 8; jj++) acc[j][jj] = 0ULL;

    // ---- prologue: tile 0 ----
    {
#pragma unroll
        for (int r = 0; r < 4; r++) {
            int idx = tid + 256*r;
            int kk = idx >> 6, nq = idx & 63;
            cp_async16(&Bs[0][kk][nq*4], We + (0 + kk)*HH + nq*4);
        }
        CP_COMMIT();
        float4 a4 = *(const float4*)(Arow + 0 + aq*4);
        As[0][aq*4+0][am] = a4.x; As[0][aq*4+1][am] = a4.y;
        As[0][aq*4+2][am] = a4.z; As[0][aq*4+3][am] = a4.w;
        CP_WAIT0();
        __syncthreads();
    }

    // ---- main loop over 32 K-tiles ----
    for (int t = 0; t < 32; t++) {
        const int cur = t & 1;
        float4 a4;
        if (t < 31) {
            const int k0 = (t+1)*16;
#pragma unroll
            for (int r = 0; r < 4; r++) {
                int idx = tid + 256*r;
                int kk = idx >> 6, nq = idx & 63;
                cp_async16(&Bs[cur^1][kk][nq*4], We + (k0 + kk)*HH + nq*4);
            }
            CP_COMMIT();
            a4 = *(const float4*)(Arow + k0 + aq*4);
        }

#pragma unroll
        for (int kk = 0; kk < 16; kk++) {
            const unsigned long long* Brow = (const unsigned long long*)&Bs[cur][kk][0];
            unsigned long long bfrag[8];
#pragma unroll
            for (int jj = 0; jj < 8; jj++) bfrag[jj] = Brow[tx + jj*16];
            unsigned long long afrag[4];
#pragma unroll
            for (int j = 0; j < 4; j++) afrag[j] = dup_f32x2(As[cur][kk][ty + j*16]);
#pragma unroll
            for (int j = 0; j < 4; j++)
#pragma unroll
                for (int jj = 0; jj < 8; jj++) fma_f32x2(acc[j][jj], afrag[j], bfrag[jj]);
        }

        if (t < 31) {
            As[cur^1][aq*4+0][am] = a4.x; As[cur^1][aq*4+1][am] = a4.y;
            As[cur^1][aq*4+2][am] = a4.z; As[cur^1][aq*4+3][am] = a4.w;
            CP_WAIT0();
        }
        __syncthreads();
    }

    // ---- epilogue: +qWh, tanh, dot v, half-warp reduce over tx ----
    float2 vv[8], qw[8];
#pragma unroll
    for (int jj = 0; jj < 8; jj++) {
        const int n0 = tx*2 + jj*32;
        vv[jj] = *(const float2*)(v + n0);
        qw[jj] = *(const float2*)(&g_qWh[b*HH + n0]);
    }
    float sc[4];
#pragma unroll
    for (int j = 0; j < 4; j++) {
        float p = 0.0f;
#pragma unroll
        for (int jj = 0; jj < 8; jj++) {
            float2 q2 = unpack_f32x2(acc[j][jj]);
            p += vv[jj].x * tanhf(q2.x + qw[jj].x);
            p += vv[jj].y * tanhf(q2.y + qw[jj].y);
        }
#pragma unroll
        for (int o = 8; o; o >>= 1) p += __shfl_xor_sync(0xffffffffu, p, o);
        sc[j] = p;
    }
    if (tx == 0) {
#pragma unroll
        for (int j = 0; j < 4; j++) g_scores[b*SS + s0 + ty + j*16] = sc[j];
    }
}

// ---------------- kernel 3: softmax over S per batch (in place) -------------
__global__ void softmax_kernel()
{
    __shared__ float red[32];
    const int b = blockIdx.x, tid = threadIdx.x;
    float* row = g_scores + b*SS;
    float4 xv = *(float4*)(row + tid*4);
    const unsigned lane = tid & 31, w = tid >> 5;

    float m = fmaxf(fmaxf(xv.x, xv.y), fmaxf(xv.z, xv.w));
#pragma unroll
    for (int o = 16; o; o >>= 1) m = fmaxf(m, __shfl_xor_sync(0xffffffffu, m, o));
    if (!lane) red[w] = m;
    __syncthreads();
    if (tid < 32) {
        float t = red[tid];
#pragma unroll
        for (int o = 16; o; o >>= 1) t = fmaxf(t, __shfl_xor_sync(0xffffffffu, t, o));
        if (!tid) red[0] = t;
    }
    __syncthreads();
    const float mm = red[0];
    __syncthreads();

    float4 ev = make_float4(expf(xv.x - mm), expf(xv.y - mm),
                            expf(xv.z - mm), expf(xv.w - mm));
    float s = ev.x + ev.y + ev.z + ev.w;
#pragma unroll
    for (int o = 16; o; o >>= 1) s += __shfl_xor_sync(0xffffffffu, s, o);
    if (!lane) red[w] = s;
    __syncthreads();
    if (tid < 32) {
        float t = red[tid];
#pragma unroll
        for (int o = 16; o; o >>= 1) t += __shfl_xor_sync(0xffffffffu, t, o);
        if (!tid) red[0] = t;
    }
    __syncthreads();
    const float inv = 1.0f / red[0];
    ev.x *= inv; ev.y *= inv; ev.z *= inv; ev.w *= inv;
    *(float4*)(row + tid*4) = ev;
}

// ---------------- kernel 4: context partials: part[c][b][f] ----------------
__global__ void ctx_kernel(const float* __restrict__ E)
{
    __shared__ float sa[SS / NCHUNK];
    const int c = blockIdx.x, b = blockIdx.y, tid = threadIdx.x; // 128 threads
    const int s0 = c * (SS / NCHUNK);
    sa[tid]       = g_scores[b*SS + s0 + tid];
    sa[tid + 128] = g_scores[b*SS + s0 + tid + 128];
    __syncthreads();

    float4 acc = make_float4(0.f, 0.f, 0.f, 0.f);
    const float* base = E + (long)(b*SS + s0) * FF + tid*4;
#pragma unroll 8
    for (int s = 0; s < SS / NCHUNK; s++) {
        const float a = sa[s];
        const float4 e = *(const float4*)(base + (long)s * FF);
        acc.x += a*e.x; acc.y += a*e.y; acc.z += a*e.z; acc.w += a*e.w;
    }
    *(float4*)(&g_part[(long)(c*BB + b)*FF + tid*4]) = acc;
}

// ---------------- kernel 5: reduce + GRU + output projection ----------------
__global__ void gru_kernel(const float* __restrict__ w_ih, const float* __restrict__ b_ih,
                           const float* __restrict__ b_hh, const float* __restrict__ out_W,
                           const float* __restrict__ out_b, float* __restrict__ out,
                           int out_size)
{
    __shared__ float x[3*HH];
    __shared__ float g[3*HH];
    __shared__ float h[HH];
    const int b = blockIdx.x, tid = threadIdx.x; // 256 threads

    // context reduce over NCHUNK partials -> x[256..767]
#pragma unroll
    for (int r = 0; r < 2; r++) {
        const int f = tid + r*256;
        float acc = 0.0f;
#pragma unroll
        for (int c = 0; c < NCHUNK; c++) acc += g_part[(long)(c*BB + b)*FF + f];
        x[HH + f] = acc;
    }
    x[tid] = g_embT[b*HH + tid];
    __syncthreads();

    // gi = x @ w_ih + b_ih   (768x768)
#pragma unroll
    for (int r = 0; r < 3; r++) {
        const int jj = tid + r*256;
        float acc = b_ih[jj];
#pragma unroll 8
        for (int k = 0; k < 3*HH; k++) acc += x[k] * w_ih[k*(3*HH) + jj];
        g[jj] = acc;
    }
    __syncthreads();

    // gates (h0 = 0  =>  gh = b_hh exactly)
    {
        const int j = tid;
        const float rg = sigmoidf_(g[j]        + b_hh[j]);
        const float zg = sigmoidf_(g[HH + j]   + b_hh[HH + j]);
        const float ng = tanhf   (g[2*HH + j]  + rg * b_hh[2*HH + j]);
        const float hv = (1.0f - zg) * ng;
        h[j] = hv;
        const int ho = BB*OUTD + b*HH + j;
        if (ho < out_size) out[ho] = hv;
    }
    __syncthreads();

    // output = h @ out_W + out_b
    if (tid < OUTD) {
        float acc = out_b[tid];
#pragma unroll 8
        for (int k = 0; k < HH; k++) acc += h[k] * out_W[k*OUTD + tid];
        out[b*OUTD + tid] = acc;
    }
}

// ---------------- launch ----------------
extern "C" void kernel_launch(void* const* d_in, const int* in_sizes, int n_in,
                              void* d_out, int out_size)
{
    const int*   fc     = (const int*)  d_in[0];   // fut_ctxt (B,1)
    const int*   ft     = (const int*)  d_in[1];   // fut_temp (B,1)
    const float* E      = (const float*)d_in[2];   // encoder_outputs (B,S,2H)
    const float* emb_c  = (const float*)d_in[3];   // emb_ctxt (1000,H)
    const float* emb_t  = (const float*)d_in[4];   // emb_temp (1000,H)
    const float* attn_W = (const float*)d_in[5];   // (3H,H)
    const float* attn_b = (const float*)d_in[6];   // (H,)
    const float* v      = (const float*)d_in[7];   // (H,)
    const float* w_ih   = (const float*)d_in[8];   // (3H,3H)
    // d_in[9] = w_hh: unused since h0 == 0 (gh = b_hh exactly)
    const float* b_ih   = (const float*)d_in[10];  // (3H,)
    const float* b_hh   = (const float*)d_in[11];  // (3H,)
    const float* out_W  = (const float*)d_in[12];  // (H,OUT)
    const float* out_b  = (const float*)d_in[13];  // (OUT,)
    float* out = (float*)d_out;

    setup_kernel<<<BB, HH>>>(fc, ft, emb_c, emb_t, attn_W, attn_b);
    scores_kernel<<<dim3(SS/64, BB), 256>>>(E, attn_W, v);
    softmax_kernel<<<BB, 1024>>>();
    ctx_kernel<<<dim3(NCHUNK, BB), 128>>>(E);
    gru_kernel<<<BB, 256>>>(w_ih, b_ih, b_hh, out_W, out_b, out, out_size);
}

// round 5
// speedup vs baseline: 1.0023x; 1.0023x over previous
#include <cuda_runtime.h>

#define BB   64
#define SS   4096
#define HH   256
#define FF   512      // 2*H
#define OUTD 24
#define NCHUNK 16     // s-chunks for context partials

// ---------------- scratch (static device globals; no allocs) ----------------
__device__ __align__(16) float g_qWh[BB*HH];      // hidden_q @ W_h + attn_b
__device__ __align__(16) float g_embT[BB*HH];     // gathered emb_temp
__device__ __align__(16) float g_scores[BB*SS];   // scores -> attn (in place)
__device__ __align__(16) float g_part[NCHUNK*BB*FF]; // context partial sums

// ---------------- helpers ----------------
__device__ __forceinline__ void cp_async16(void* sm, const void* g) {
    unsigned s = (unsigned)__cvta_generic_to_shared(sm);
    asm volatile("cp.async.cg.shared.global [%0], [%1], 16;" :: "r"(s), "l"(g));
}
#define CP_COMMIT() asm volatile("cp.async.commit_group;")
#define CP_WAIT0()  asm volatile("cp.async.wait_group 0;")

__device__ __forceinline__ unsigned long long dup_f32x2(float a) {
    unsigned long long r;
    unsigned ai = __float_as_uint(a);
    asm("mov.b64 %0, {%1, %1};" : "=l"(r) : "r"(ai));
    return r;
}
__device__ __forceinline__ void fma_f32x2(unsigned long long& acc,
                                          unsigned long long a,
                                          unsigned long long b) {
    asm("fma.rn.f32x2 %0, %1, %2, %0;" : "+l"(acc) : "l"(a), "l"(b));
}
__device__ __forceinline__ float2 unpack_f32x2(unsigned long long p) {
    unsigned lo, hi;
    asm("mov.b64 {%0, %1}, %2;" : "=r"(lo), "=r"(hi) : "l"(p));
    return make_float2(__uint_as_float(lo), __uint_as_float(hi));
}
__device__ __forceinline__ float sigmoidf_(float x) { return 1.0f / (1.0f + expf(-x)); }

// ---------------- kernel 1: gathers + qWh = emb_ctxt[idx] @ W_h + attn_b ----
__global__ void setup_kernel(const int* __restrict__ fc, const int* __restrict__ ft,
                             const float* __restrict__ emb_c, const float* __restrict__ emb_t,
                             const float* __restrict__ attn_W, const float* __restrict__ attn_b)
{
    __shared__ float q[HH];
    int b = blockIdx.x, tid = threadIdx.x;
    int ci = fc[b], ti = ft[b];
    q[tid] = emb_c[ci*HH + tid];
    g_embT[b*HH + tid] = emb_t[ti*HH + tid];
    __syncthreads();
    float acc = attn_b[tid];
#pragma unroll 8
    for (int k = 0; k < HH; k++) acc += q[k] * attn_W[k*HH + tid];
    g_qWh[b*HH + tid] = acc;
}

// ---------------- kernel 2: fused scores GEMM ----------------
// scores[b][s] = v . tanh( qWh[b] + E[b,s,:] @ W_e )
// CTA tile: 64 s-rows x 256 H-cols x K=512 (BK=16, double buffered).
// 256 threads = 16(tx: n) x 16(ty: m); thread tile 4m x 16n (8 f32x2 pairs).
__global__ void __launch_bounds__(256, 2)
scores_kernel(const float* __restrict__ E, const float* __restrict__ attn_W,
              const float* __restrict__ v)
{
    __shared__ float As[2][16][65];    // [k][m] (+pad) transposed E tile
    __shared__ float Bs[2][16][256];   // [k][n] W_e tile

    const int b  = blockIdx.y;
    const int s0 = blockIdx.x * 64;
    const int tid = threadIdx.x;
    const int tx = tid & 15, ty = tid >> 4;

    const float* We = attn_W + HH*HH;  // W_e = attn_W rows [256, 768)

    // A load indices: each thread one float4 per tile
    const int am = tid >> 2, aq = tid & 3;
    const float* Arow = E + (long)(b*SS + s0 + am) * FF;

    unsigned long long acc[4][8];
#pragma unroll
    for (int j = 0; j < 4; j++)
#pragma unroll
        for (int jj = 0; jj < 8; jj++) acc[j][jj] = 0ULL;

    // ---- prologue: tile 0 ----
    {
#pragma unroll
        for (int r = 0; r < 4; r++) {
            int idx = tid + 256*r;
            int kk = idx >> 6, nq = idx & 63;
            cp_async16(&Bs[0][kk][nq*4], We + (0 + kk)*HH + nq*4);
        }
        CP_COMMIT();
        float4 a4 = *(const float4*)(Arow + 0 + aq*4);
        As[0][aq*4+0][am] = a4.x; As[0][aq*4+1][am] = a4.y;
        As[0][aq*4+2][am] = a4.z; As[0][aq*4+3][am] = a4.w;
        CP_WAIT0();
        __syncthreads();
    }

    // ---- main loop over 32 K-tiles ----
    for (int t = 0; t < 32; t++) {
        const int cur = t & 1;
        float4 a4;
        if (t < 31) {
            const int k0 = (t+1)*16;
#pragma unroll
            for (int r = 0; r < 4; r++) {
                int idx = tid + 256*r;
                int kk = idx >> 6, nq = idx & 63;
                cp_async16(&Bs[cur^1][kk][nq*4], We + (k0 + kk)*HH + nq*4);
            }
            CP_COMMIT();
            a4 = *(const float4*)(Arow + k0 + aq*4);
        }

#pragma unroll
        for (int kk = 0; kk < 16; kk++) {
            const unsigned long long* Brow = (const unsigned long long*)&Bs[cur][kk][0];
            unsigned long long bfrag[8];
#pragma unroll
            for (int jj = 0; jj < 8; jj++) bfrag[jj] = Brow[tx + jj*16];
            unsigned long long afrag[4];
#pragma unroll
            for (int j = 0; j < 4; j++) afrag[j] = dup_f32x2(As[cur][kk][ty + j*16]);
#pragma unroll
            for (int j = 0; j < 4; j++)
#pragma unroll
                for (int jj = 0; jj < 8; jj++) fma_f32x2(acc[j][jj], afrag[j], bfrag[jj]);
        }

        if (t < 31) {
            As[cur^1][aq*4+0][am] = a4.x; As[cur^1][aq*4+1][am] = a4.y;
            As[cur^1][aq*4+2][am] = a4.z; As[cur^1][aq*4+3][am] = a4.w;
            CP_WAIT0();
        }
        __syncthreads();
    }

    // ---- epilogue: +qWh, tanh, dot v, half-warp reduce over tx ----
    float2 vv[8], qw[8];
#pragma unroll
    for (int jj = 0; jj < 8; jj++) {
        const int n0 = tx*2 + jj*32;
        vv[jj] = *(const float2*)(v + n0);
        qw[jj] = *(const float2*)(&g_qWh[b*HH + n0]);
    }
    float sc[4];
#pragma unroll
    for (int j = 0; j < 4; j++) {
        float p = 0.0f;
#pragma unroll
        for (int jj = 0; jj < 8; jj++) {
            float2 q2 = unpack_f32x2(acc[j][jj]);
            p += vv[jj].x * tanhf(q2.x + qw[jj].x);
            p += vv[jj].y * tanhf(q2.y + qw[jj].y);
        }
#pragma unroll
        for (int o = 8; o; o >>= 1) p += __shfl_xor_sync(0xffffffffu, p, o);
        sc[j] = p;
    }
    if (tx == 0) {
#pragma unroll
        for (int j = 0; j < 4; j++) g_scores[b*SS + s0 + ty + j*16] = sc[j];
    }
}

// ---------------- kernel 3: softmax over S per batch (in place) -------------
__global__ void softmax_kernel()
{
    __shared__ float red[32];
    const int b = blockIdx.x, tid = threadIdx.x;
    float* row = g_scores + b*SS;
    float4 xv = *(float4*)(row + tid*4);
    const unsigned lane = tid & 31, w = tid >> 5;

    float m = fmaxf(fmaxf(xv.x, xv.y), fmaxf(xv.z, xv.w));
#pragma unroll
    for (int o = 16; o; o >>= 1) m = fmaxf(m, __shfl_xor_sync(0xffffffffu, m, o));
    if (!lane) red[w] = m;
    __syncthreads();
    if (tid < 32) {
        float t = red[tid];
#pragma unroll
        for (int o = 16; o; o >>= 1) t = fmaxf(t, __shfl_xor_sync(0xffffffffu, t, o));
        if (!tid) red[0] = t;
    }
    __syncthreads();
    const float mm = red[0];
    __syncthreads();

    float4 ev = make_float4(expf(xv.x - mm), expf(xv.y - mm),
                            expf(xv.z - mm), expf(xv.w - mm));
    float s = ev.x + ev.y + ev.z + ev.w;
#pragma unroll
    for (int o = 16; o; o >>= 1) s += __shfl_xor_sync(0xffffffffu, s, o);
    if (!lane) red[w] = s;
    __syncthreads();
    if (tid < 32) {
        float t = red[tid];
#pragma unroll
        for (int o = 16; o; o >>= 1) t += __shfl_xor_sync(0xffffffffu, t, o);
        if (!tid) red[0] = t;
    }
    __syncthreads();
    const float inv = 1.0f / red[0];
    ev.x *= inv; ev.y *= inv; ev.z *= inv; ev.w *= inv;
    *(float4*)(row + tid*4) = ev;
}

// ---------------- kernel 4: context partials: part[c][b][f] ----------------
__global__ void ctx_kernel(const float* __restrict__ E)
{
    __shared__ float sa[SS / NCHUNK];
    const int c = blockIdx.x, b = blockIdx.y, tid = threadIdx.x; // 128 threads
    const int s0 = c * (SS / NCHUNK);
    sa[tid]       = g_scores[b*SS + s0 + tid];
    sa[tid + 128] = g_scores[b*SS + s0 + tid + 128];
    __syncthreads();

    float4 acc = make_float4(0.f, 0.f, 0.f, 0.f);
    const float* base = E + (long)(b*SS + s0) * FF + tid*4;
#pragma unroll 8
    for (int s = 0; s < SS / NCHUNK; s++) {
        const float a = sa[s];
        const float4 e = *(const float4*)(base + (long)s * FF);
        acc.x += a*e.x; acc.y += a*e.y; acc.z += a*e.z; acc.w += a*e.w;
    }
    *(float4*)(&g_part[(long)(c*BB + b)*FF + tid*4]) = acc;
}

// ---------------- kernel 5: reduce + GRU + output projection ----------------
__global__ void gru_kernel(const float* __restrict__ w_ih, const float* __restrict__ b_ih,
                           const float* __restrict__ b_hh, const float* __restrict__ out_W,
                           const float* __restrict__ out_b, float* __restrict__ out,
                           int out_size)
{
    __shared__ float x[3*HH];
    __shared__ float g[3*HH];
    __shared__ float h[HH];
    const int b = blockIdx.x, tid = threadIdx.x; // 256 threads

    // context reduce over NCHUNK partials -> x[256..767]
#pragma unroll
    for (int r = 0; r < 2; r++) {
        const int f = tid + r*256;
        float acc = 0.0f;
#pragma unroll
        for (int c = 0; c < NCHUNK; c++) acc += g_part[(long)(c*BB + b)*FF + f];
        x[HH + f] = acc;
    }
    x[tid] = g_embT[b*HH + tid];
    __syncthreads();

    // gi = x @ w_ih + b_ih   (768x768)
#pragma unroll
    for (int r = 0; r < 3; r++) {
        const int jj = tid + r*256;
        float acc = b_ih[jj];
#pragma unroll 8
        for (int k = 0; k < 3*HH; k++) acc += x[k] * w_ih[k*(3*HH) + jj];
        g[jj] = acc;
    }
    __syncthreads();

    // gates (h0 = 0  =>  gh = b_hh exactly)
    {
        const int j = tid;
        const float rg = sigmoidf_(g[j]        + b_hh[j]);
        const float zg = sigmoidf_(g[HH + j]   + b_hh[HH + j]);
        const float ng = tanhf   (g[2*HH + j]  + rg * b_hh[2*HH + j]);
        const float hv = (1.0f - zg) * ng;
        h[j] = hv;
        const int ho = BB*OUTD + b*HH + j;
        if (ho < out_size) out[ho] = hv;
    }
    __syncthreads();

    // output = h @ out_W + out_b
    if (tid < OUTD) {
        float acc = out_b[tid];
#pragma unroll 8
        for (int k = 0; k < HH; k++) acc += h[k] * out_W[k*OUTD + tid];
        out[b*OUTD + tid] = acc;
    }
}

// ---------------- launch ----------------
extern "C" void kernel_launch(void* const* d_in, const int* in_sizes, int n_in,
                              void* d_out, int out_size)
{
    const int*   fc     = (const int*)  d_in[0];   // fut_ctxt (B,1)
    const int*   ft     = (const int*)  d_in[1];   // fut_temp (B,1)
    const float* E      = (const float*)d_in[2];   // encoder_outputs (B,S,2H)
    const float* emb_c  = (const float*)d_in[3];   // emb_ctxt (1000,H)
    const float* emb_t  = (const float*)d_in[4];   // emb_temp (1000,H)
    const float* attn_W = (const float*)d_in[5];   // (3H,H)
    const float* attn_b = (const float*)d_in[6];   // (H,)
    const float* v      = (const float*)d_in[7];   // (H,)
    const float* w_ih   = (const float*)d_in[8];   // (3H,3H)
    // d_in[9] = w_hh: unused since h0 == 0 (gh = b_hh exactly)
    const float* b_ih   = (const float*)d_in[10];  // (3H,)
    const float* b_hh   = (const float*)d_in[11];  // (3H,)
    const float* out_W  = (const float*)d_in[12];  // (H,OUT)
    const float* out_b  = (const float*)d_in[13];  // (OUT,)
    float* out = (float*)d_out;

    setup_kernel<<<BB, HH>>>(fc, ft, emb_c, emb_t, attn_W, attn_b);
    scores_kernel<<<dim3(SS/64, BB), 256>>>(E, attn_W, v);
    softmax_kernel<<<BB, 1024>>>();
    ctx_kernel<<<dim3(NCHUNK, BB), 128>>>(E);
    gru_kernel<<<BB, 256>>>(w_ih, b_ih, b_hh, out_W, out_b, out, out_size);
}

// round 7
// speedup vs baseline: 1.8319x; 1.8277x over previous
#include <cuda_runtime.h>
#include <cuda_bf16.h>
#include <cstdint>

#define BB   64
#define SS   4096
#define HH   256
#define FF   512      // 2*H
#define OUTD 24
#define NCHUNK 16     // s-chunks for context partials

// ---------------- scratch (static device globals; no allocs) ----------------
__device__ __align__(16) float g_qWh[BB*HH];      // hidden_q @ W_h + attn_b
__device__ __align__(16) float g_embT[BB*HH];     // gathered emb_temp
__device__ __align__(16) float g_scores[BB*SS];   // attn weights (post-softmax)
__device__ __align__(16) float g_spart[2*BB*SS];  // score partials per n-half
__device__ __align__(16) float g_part[NCHUNK*BB*FF]; // context partial sums
__device__ __align__(16) __nv_bfloat16 g_Wb_hi[HH*FF]; // W_e^T hi split [n=256][k=512]
__device__ __align__(16) __nv_bfloat16 g_Wb_lo[HH*FF]; // W_e^T lo split

// ---------------- helpers ----------------
__device__ __forceinline__ uint32_t smem_u32(const void* p) {
    uint32_t a;
    asm("{ .reg .u64 t; cvta.to.shared.u64 t, %1; cvt.u32.u64 %0, t; }"
        : "=r"(a) : "l"(p));
    return a;
}
__device__ __forceinline__ void cp_async16(void* sm, const void* g) {
    unsigned s = (unsigned)__cvta_generic_to_shared(sm);
    asm volatile("cp.async.cg.shared.global [%0], [%1], 16;" :: "r"(s), "l"(g));
}
#define CP_COMMIT() asm volatile("cp.async.commit_group;")
#define CP_WAIT0()  asm volatile("cp.async.wait_group 0;")

__device__ __forceinline__ void ldsm_x4(uint32_t* r, uint32_t addr) {
    asm volatile("ldmatrix.sync.aligned.m8n8.x4.shared.b16 {%0,%1,%2,%3}, [%4];"
        : "=r"(r[0]), "=r"(r[1]), "=r"(r[2]), "=r"(r[3]) : "r"(addr));
}
__device__ __forceinline__ void mma_bf16(float* c, const uint32_t* a, const uint32_t* b) {
    asm volatile("mma.sync.aligned.m16n8k16.row.col.f32.bf16.bf16.f32 "
        "{%0,%1,%2,%3}, {%4,%5,%6,%7}, {%8,%9}, {%0,%1,%2,%3};"
        : "+f"(c[0]), "+f"(c[1]), "+f"(c[2]), "+f"(c[3])
        : "r"(a[0]), "r"(a[1]), "r"(a[2]), "r"(a[3]), "r"(b[0]), "r"(b[1]));
}
// conflict-free 64B-row swizzle: 16B chunk c (0..3) of row r
__device__ __forceinline__ uint32_t swoff(int r, int c) {
    return (uint32_t)(r*64 + ((c ^ ((r >> 1) & 3)) << 4));
}
__device__ __forceinline__ void split2(float x0, float x1, uint32_t& h, uint32_t& l) {
    __nv_bfloat162 hp = __floats2bfloat162_rn(x0, x1);
    float r0 = x0 - __bfloat162float(hp.x);
    float r1 = x1 - __bfloat162float(hp.y);
    __nv_bfloat162 lp = __floats2bfloat162_rn(r0, r1);
    h = *reinterpret_cast<uint32_t*>(&hp);
    l = *reinterpret_cast<uint32_t*>(&lp);
}
__device__ __forceinline__ float sigmoidf_(float x) { return 1.0f / (1.0f + expf(-x)); }

// ---------------- kernel 1: gathers + qWh = emb_ctxt[idx] @ W_h + attn_b ----
__global__ void setup_kernel(const int* __restrict__ fc, const int* __restrict__ ft,
                             const float* __restrict__ emb_c, const float* __restrict__ emb_t,
                             const float* __restrict__ attn_W, const float* __restrict__ attn_b)
{
    __shared__ float q[HH];
    int b = blockIdx.x, tid = threadIdx.x;
    int ci = fc[b], ti = ft[b];
    q[tid] = emb_c[ci*HH + tid];
    g_embT[b*HH + tid] = emb_t[ti*HH + tid];
    __syncthreads();
    float acc = attn_b[tid];
#pragma unroll 8
    for (int k = 0; k < HH; k++) acc += q[k] * attn_W[k*HH + tid];
    g_qWh[b*HH + tid] = acc;
}

// ---------------- kernel 1b: W_e transpose + bf16 hi/lo split ----------------
__global__ void prep_W(const float* __restrict__ attn_W)
{
    const float* We = attn_W + HH*HH;                  // [k=512][n=256]
    int idx = blockIdx.x * 256 + threadIdx.x;          // 131072
    int k = idx >> 8, n = idx & 255;
    float x = We[k*HH + n];
    __nv_bfloat16 hi = __float2bfloat16(x);
    __nv_bfloat16 lo = __float2bfloat16(x - __bfloat162float(hi));
    g_Wb_hi[n*FF + k] = hi;
    g_Wb_lo[n*FF + k] = lo;
}

// ---------------- kernel 2: mma.sync bf16-split scores GEMM ----------------
// Per CTA: 128 s-rows x 128 h-cols (one n-half) x K=512.
// 8 warps (2m x 4n), warp tile 64x32, 3 MMAs (hi*hi, hi*lo, lo*hi), fp32 acc.
#define STAGE   32768
#define A_HI    0
#define A_LO    8192
#define B_HI    16384
#define B_LO    24576
#define SM_QW   65536
#define SM_V    66048
#define SM_RED  66560
#define SMEM_SC 68608

__global__ void __launch_bounds__(256, 1)
scores_mma(const float* __restrict__ E, const float* __restrict__ v)
{
    extern __shared__ char sm[];
    const uint32_t smb = smem_u32(sm);
    const int tid  = threadIdx.x;
    const int lane = tid & 31, warp = tid >> 5;
    const int wm = warp >> 2, wn = warp & 3;       // 2 x 4 warp grid
    const int s0 = blockIdx.x * 128;
    const int half = blockIdx.y;
    const int b = blockIdx.z;
    const int nbase = half * 128;

    float* sq = (float*)(sm + SM_QW);
    float* sv = (float*)(sm + SM_V);
    if (tid < 128) {
        sq[tid] = g_qWh[b*HH + nbase + tid];
        sv[tid] = v[nbase + tid];
    }

    // A producer mapping: 2 units/thread, 32B fp32 each
    const int seg  = tid & 3;           // 8-float segment within 32-float row
    const int row0 = tid >> 2;          // 0..63  (second unit: row0+64)
    const float* Ap0 = E + ((long)(b*SS + s0 + row0))*FF + seg*8;
    const float* Ap1 = Ap0 + (long)64*FF;

    float acc[4][4][4];
#pragma unroll
    for (int mt = 0; mt < 4; mt++)
#pragma unroll
        for (int nt = 0; nt < 4; nt++)
#pragma unroll
            for (int e = 0; e < 4; e++) acc[mt][nt][e] = 0.0f;

    // ---- prologue: produce chunk 0 into stage 0 ----
    {
        char* stp = sm;
#pragma unroll
        for (int j = 0; j < 2; j++) {
            int idx = tid + 256*j;
            int br = idx >> 2, bc = idx & 3;
            uint32_t d = swoff(br, bc);
            long so = (long)(nbase + br)*FF + bc*8;
            cp_async16(stp + B_HI + d, g_Wb_hi + so);
            cp_async16(stp + B_LO + d, g_Wb_lo + so);
        }
        CP_COMMIT();
        float4 f00 = *(const float4*)(Ap0);
        float4 f01 = *(const float4*)(Ap0 + 4);
        float4 f10 = *(const float4*)(Ap1);
        float4 f11 = *(const float4*)(Ap1 + 4);
        uint32_t H[4], L[4];
        split2(f00.x, f00.y, H[0], L[0]); split2(f00.z, f00.w, H[1], L[1]);
        split2(f01.x, f01.y, H[2], L[2]); split2(f01.z, f01.w, H[3], L[3]);
        uint32_t d0 = swoff(row0, seg);
        *(uint4*)(stp + A_HI + d0) = make_uint4(H[0], H[1], H[2], H[3]);
        *(uint4*)(stp + A_LO + d0) = make_uint4(L[0], L[1], L[2], L[3]);
        split2(f10.x, f10.y, H[0], L[0]); split2(f10.z, f10.w, H[1], L[1]);
        split2(f11.x, f11.y, H[2], L[2]); split2(f11.z, f11.w, H[3], L[3]);
        uint32_t d1 = swoff(row0 + 64, seg);
        *(uint4*)(stp + A_HI + d1) = make_uint4(H[0], H[1], H[2], H[3]);
        *(uint4*)(stp + A_LO + d1) = make_uint4(L[0], L[1], L[2], L[3]);
        CP_WAIT0();
        __syncthreads();
    }

    for (int c = 0; c < 16; c++) {
        const int cur = c & 1;
        char* stn = sm + (cur ^ 1)*STAGE;
        const uint32_t stcb = smb + cur*STAGE;
        float4 f00, f01, f10, f11;
        if (c < 15) {
            const int k1 = (c + 1)*32;
#pragma unroll
            for (int j = 0; j < 2; j++) {
                int idx = tid + 256*j;
                int br = idx >> 2, bc = idx & 3;
                uint32_t d = swoff(br, bc);
                long so = (long)(nbase + br)*FF + k1 + bc*8;
                cp_async16(stn + B_HI + d, g_Wb_hi + so);
                cp_async16(stn + B_LO + d, g_Wb_lo + so);
            }
            CP_COMMIT();
            f00 = *(const float4*)(Ap0 + k1);
            f01 = *(const float4*)(Ap0 + k1 + 4);
            f10 = *(const float4*)(Ap1 + k1);
            f11 = *(const float4*)(Ap1 + k1 + 4);
        }

        // ---- MMAs on stage cur (2 k16-steps) ----
#pragma unroll
        for (int ks = 0; ks < 2; ks++) {
            uint32_t ah[4][4], al[4][4];
#pragma unroll
            for (int mt = 0; mt < 4; mt++) {
                int r  = wm*64 + mt*16 + (lane & 15);
                int c16 = ks*2 + (lane >> 4);
                uint32_t o = swoff(r, c16);
                ldsm_x4(ah[mt], stcb + A_HI + o);
                ldsm_x4(al[mt], stcb + A_LO + o);
            }
            uint32_t bh[4][2], bl[4][2];
#pragma unroll
            for (int np = 0; np < 2; np++) {
                int nr  = wn*32 + np*16 + ((lane >> 4) << 3) + (lane & 7);
                int c16 = ks*2 + ((lane >> 3) & 1);
                uint32_t o = swoff(nr, c16);
                uint32_t r4[4];
                ldsm_x4(r4, stcb + B_HI + o);
                bh[np*2][0] = r4[0]; bh[np*2][1] = r4[1];
                bh[np*2+1][0] = r4[2]; bh[np*2+1][1] = r4[3];
                ldsm_x4(r4, stcb + B_LO + o);
                bl[np*2][0] = r4[0]; bl[np*2][1] = r4[1];
                bl[np*2+1][0] = r4[2]; bl[np*2+1][1] = r4[3];
            }
#pragma unroll
            for (int mt = 0; mt < 4; mt++)
#pragma unroll
                for (int nt = 0; nt < 4; nt++) mma_bf16(acc[mt][nt], ah[mt], bh[nt]);
#pragma unroll
            for (int mt = 0; mt < 4; mt++)
#pragma unroll
                for (int nt = 0; nt < 4; nt++) mma_bf16(acc[mt][nt], ah[mt], bl[nt]);
#pragma unroll
            for (int mt = 0; mt < 4; mt++)
#pragma unroll
                for (int nt = 0; nt < 4; nt++) mma_bf16(acc[mt][nt], al[mt], bh[nt]);
        }

        if (c < 15) {
            uint32_t H[4], L[4];
            split2(f00.x, f00.y, H[0], L[0]); split2(f00.z, f00.w, H[1], L[1]);
            split2(f01.x, f01.y, H[2], L[2]); split2(f01.z, f01.w, H[3], L[3]);
            uint32_t d0 = swoff(row0, seg);
            *(uint4*)(stn + A_HI + d0) = make_uint4(H[0], H[1], H[2], H[3]);
            *(uint4*)(stn + A_LO + d0) = make_uint4(L[0], L[1], L[2], L[3]);
            split2(f10.x, f10.y, H[0], L[0]); split2(f10.z, f10.w, H[1], L[1]);
            split2(f11.x, f11.y, H[2], L[2]); split2(f11.z, f11.w, H[3], L[3]);
            uint32_t d1 = swoff(row0 + 64, seg);
            *(uint4*)(stn + A_HI + d1) = make_uint4(H[0], H[1], H[2], H[3]);
            *(uint4*)(stn + A_LO + d1) = make_uint4(L[0], L[1], L[2], L[3]);
            CP_WAIT0();
        }
        __syncthreads();
    }

    // ---- epilogue: +qWh, tanh, dot v over this n-half ----
    float* red = (float*)(sm + SM_RED);   // [128 rows][4 nwarps]
#pragma unroll
    for (int mt = 0; mt < 4; mt++) {
        float pA = 0.0f, pB = 0.0f;
#pragma unroll
        for (int nt = 0; nt < 4; nt++) {
            int h0 = wn*32 + nt*8 + (lane & 3)*2;
            float q0 = sq[h0], q1 = sq[h0 + 1];
            float v0 = sv[h0], v1 = sv[h0 + 1];
            pA += v0*tanhf(acc[mt][nt][0] + q0) + v1*tanhf(acc[mt][nt][1] + q1);
            pB += v0*tanhf(acc[mt][nt][2] + q0) + v1*tanhf(acc[mt][nt][3] + q1);
        }
        pA += __shfl_xor_sync(0xffffffffu, pA, 1);
        pA += __shfl_xor_sync(0xffffffffu, pA, 2);
        pB += __shfl_xor_sync(0xffffffffu, pB, 1);
        pB += __shfl_xor_sync(0xffffffffu, pB, 2);
        if ((lane & 3) == 0) {
            int r = wm*64 + mt*16 + (lane >> 2);
            red[r*4 + wn]       = pA;
            red[(r + 8)*4 + wn] = pB;
        }
    }
    __syncthreads();
    if (tid < 128) {
        float s = red[tid*4] + red[tid*4+1] + red[tid*4+2] + red[tid*4+3];
        g_spart[((long)half*BB + b)*SS + s0 + tid] = s;
    }
}

// ---------------- kernel 3: sum halves + softmax -> g_scores ----------------
__global__ void softmax_kernel()
{
    __shared__ float red[32];
    const int b = blockIdx.x, tid = threadIdx.x;
    const float* p0 = g_spart + (long)b*SS;
    const float* p1 = g_spart + (long)(BB + b)*SS;
    float4 a0 = *(const float4*)(p0 + tid*4);
    float4 a1 = *(const float4*)(p1 + tid*4);
    float4 xv = make_float4(a0.x + a1.x, a0.y + a1.y, a0.z + a1.z, a0.w + a1.w);
    const unsigned lane = tid & 31, w = tid >> 5;

    float mx = fmaxf(fmaxf(xv.x, xv.y), fmaxf(xv.z, xv.w));
#pragma unroll
    for (int o = 16; o; o >>= 1) mx = fmaxf(mx, __shfl_xor_sync(0xffffffffu, mx, o));
    if (!lane) red[w] = mx;
    __syncthreads();
    if (tid < 32) {
        float t = red[tid];
#pragma unroll
        for (int o = 16; o; o >>= 1) t = fmaxf(t, __shfl_xor_sync(0xffffffffu, t, o));
        if (!tid) red[0] = t;
    }
    __syncthreads();
    const float mm = red[0];
    __syncthreads();

    float4 ev = make_float4(expf(xv.x - mm), expf(xv.y - mm),
                            expf(xv.z - mm), expf(xv.w - mm));
    float s = ev.x + ev.y + ev.z + ev.w;
#pragma unroll
    for (int o = 16; o; o >>= 1) s += __shfl_xor_sync(0xffffffffu, s, o);
    if (!lane) red[w] = s;
    __syncthreads();
    if (tid < 32) {
        float t = red[tid];
#pragma unroll
        for (int o = 16; o; o >>= 1) t += __shfl_xor_sync(0xffffffffu, t, o);
        if (!tid) red[0] = t;
    }
    __syncthreads();
    const float inv = 1.0f / red[0];
    ev.x *= inv; ev.y *= inv; ev.z *= inv; ev.w *= inv;
    *(float4*)(g_scores + b*SS + tid*4) = ev;
}

// ---------------- kernel 4: context partials: part[c][b][f] ----------------
__global__ void ctx_kernel(const float* __restrict__ E)
{
    __shared__ float sa[SS / NCHUNK];
    const int c = blockIdx.x, b = blockIdx.y, tid = threadIdx.x; // 128 threads
    const int s0 = c * (SS / NCHUNK);
    sa[tid]       = g_scores[b*SS + s0 + tid];
    sa[tid + 128] = g_scores[b*SS + s0 + tid + 128];
    __syncthreads();

    float4 acc = make_float4(0.f, 0.f, 0.f, 0.f);
    const float* base = E + (long)(b*SS + s0) * FF + tid*4;
#pragma unroll 8
    for (int s = 0; s < SS / NCHUNK; s++) {
        const float a = sa[s];
        const float4 e = *(const float4*)(base + (long)s * FF);
        acc.x += a*e.x; acc.y += a*e.y; acc.z += a*e.z; acc.w += a*e.w;
    }
    *(float4*)(&g_part[(long)(c*BB + b)*FF + tid*4]) = acc;
}

// ---------------- kernel 5: reduce + GRU + output projection ----------------
__global__ void gru_kernel(const float* __restrict__ w_ih, const float* __restrict__ b_ih,
                           const float* __restrict__ b_hh, const float* __restrict__ out_W,
                           const float* __restrict__ out_b, float* __restrict__ out,
                           int out_size)
{
    __shared__ float x[3*HH];
    __shared__ float g[3*HH];
    __shared__ float h[HH];
    const int b = blockIdx.x, tid = threadIdx.x; // 256 threads

#pragma unroll
    for (int r = 0; r < 2; r++) {
        const int f = tid + r*256;
        float acc = 0.0f;
#pragma unroll
        for (int c = 0; c < NCHUNK; c++) acc += g_part[(long)(c*BB + b)*FF + f];
        x[HH + f] = acc;
    }
    x[tid] = g_embT[b*HH + tid];
    __syncthreads();

#pragma unroll
    for (int r = 0; r < 3; r++) {
        const int jj = tid + r*256;
        float acc = b_ih[jj];
#pragma unroll 8
        for (int k = 0; k < 3*HH; k++) acc += x[k] * w_ih[k*(3*HH) + jj];
        g[jj] = acc;
    }
    __syncthreads();

    {
        const int j = tid;
        const float rg = sigmoidf_(g[j]        + b_hh[j]);
        const float zg = sigmoidf_(g[HH + j]   + b_hh[HH + j]);
        const float ng = tanhf   (g[2*HH + j]  + rg * b_hh[2*HH + j]);
        const float hv = (1.0f - zg) * ng;
        h[j] = hv;
        const int ho = BB*OUTD + b*HH + j;
        if (ho < out_size) out[ho] = hv;
    }
    __syncthreads();

    if (tid < OUTD) {
        float acc = out_b[tid];
#pragma unroll 8
        for (int k = 0; k < HH; k++) acc += h[k] * out_W[k*OUTD + tid];
        out[b*OUTD + tid] = acc;
    }
}

// ---------------- launch ----------------
extern "C" void kernel_launch(void* const* d_in, const int* in_sizes, int n_in,
                              void* d_out, int out_size)
{
    const int*   fc     = (const int*)  d_in[0];   // fut_ctxt (B,1)
    const int*   ft     = (const int*)  d_in[1];   // fut_temp (B,1)
    const float* E      = (const float*)d_in[2];   // encoder_outputs (B,S,2H)
    const float* emb_c  = (const float*)d_in[3];   // emb_ctxt (1000,H)
    const float* emb_t  = (const float*)d_in[4];   // emb_temp (1000,H)
    const float* attn_W = (const float*)d_in[5];   // (3H,H)
    const float* attn_b = (const float*)d_in[6];   // (H,)
    const float* v      = (const float*)d_in[7];   // (H,)
    const float* w_ih   = (const float*)d_in[8];   // (3H,3H)
    // d_in[9] = w_hh: unused since h0 == 0 (gh = b_hh exactly)
    const float* b_ih   = (const float*)d_in[10];  // (3H,)
    const float* b_hh   = (const float*)d_in[11];  // (3H,)
    const float* out_W  = (const float*)d_in[12];  // (H,OUT)
    const float* out_b  = (const float*)d_in[13];  // (OUT,)
    float* out = (float*)d_out;

    cudaFuncSetAttribute(scores_mma, cudaFuncAttributeMaxDynamicSharedMemorySize,
                         SMEM_SC);

    setup_kernel<<<BB, HH>>>(fc, ft, emb_c, emb_t, attn_W, attn_b);
    prep_W<<<512, 256>>>(attn_W);
    scores_mma<<<dim3(SS/128, 2, BB), 256, SMEM_SC>>>(E, v);
    softmax_kernel<<<BB, 1024>>>();
    ctx_kernel<<<dim3(NCHUNK, BB), 128>>>(E);
    gru_kernel<<<BB, 256>>>(w_ih, b_ih, b_hh, out_W, out_b, out, out_size);
}

// round 8
// speedup vs baseline: 1.9373x; 1.0576x over previous
#include <cuda_runtime.h>
#include <cuda_bf16.h>
#include <cstdint>

#define BB   64
#define SS   4096
#define HH   256
#define FF   512      // 2*H
#define OUTD 24
#define NCHUNK 16     // s-chunks for context partials

// ---------------- scratch (static device globals; no allocs) ----------------
__device__ __align__(16) float g_qWh[BB*HH];      // hidden_q @ W_h + attn_b
__device__ __align__(16) float g_embT[BB*HH];     // gathered emb_temp
__device__ __align__(16) float g_scores[BB*SS];   // attn weights (post-softmax)
__device__ __align__(16) float g_spart[BB*SS];    // pre-softmax scores
__device__ __align__(16) float g_part[NCHUNK*BB*FF]; // context partial sums
__device__ __align__(16) __nv_bfloat16 g_Wb_hi[HH*FF]; // W_e^T hi split [n=256][k=512]
__device__ __align__(16) __nv_bfloat16 g_Wb_lo[HH*FF]; // W_e^T lo split

// ---------------- helpers ----------------
__device__ __forceinline__ uint32_t smem_u32(const void* p) {
    uint32_t a;
    asm("{ .reg .u64 t; cvta.to.shared.u64 t, %1; cvt.u32.u64 %0, t; }"
        : "=r"(a) : "l"(p));
    return a;
}
__device__ __forceinline__ void cp_async16(void* sm, const void* g) {
    unsigned s = (unsigned)__cvta_generic_to_shared(sm);
    asm volatile("cp.async.cg.shared.global [%0], [%1], 16;" :: "r"(s), "l"(g));
}
#define CP_COMMIT() asm volatile("cp.async.commit_group;")
#define CP_WAIT0()  asm volatile("cp.async.wait_group 0;")

__device__ __forceinline__ void ldsm_x4(uint32_t* r, uint32_t addr) {
    asm volatile("ldmatrix.sync.aligned.m8n8.x4.shared.b16 {%0,%1,%2,%3}, [%4];"
        : "=r"(r[0]), "=r"(r[1]), "=r"(r[2]), "=r"(r[3]) : "r"(addr));
}
__device__ __forceinline__ void mma_bf16(float* c, const uint32_t* a, const uint32_t* b) {
    asm volatile("mma.sync.aligned.m16n8k16.row.col.f32.bf16.bf16.f32 "
        "{%0,%1,%2,%3}, {%4,%5,%6,%7}, {%8,%9}, {%0,%1,%2,%3};"
        : "+f"(c[0]), "+f"(c[1]), "+f"(c[2]), "+f"(c[3])
        : "r"(a[0]), "r"(a[1]), "r"(a[2]), "r"(a[3]), "r"(b[0]), "r"(b[1]));
}
// conflict-free 64B-row swizzle: 16B chunk c (0..3) of row r
__device__ __forceinline__ uint32_t swoff(int r, int c) {
    return (uint32_t)(r*64 + ((c ^ ((r >> 1) & 3)) << 4));
}
__device__ __forceinline__ void split2(float x0, float x1, uint32_t& h, uint32_t& l) {
    __nv_bfloat162 hp = __floats2bfloat162_rn(x0, x1);
    float r0 = x0 - __bfloat162float(hp.x);
    float r1 = x1 - __bfloat162float(hp.y);
    __nv_bfloat162 lp = __floats2bfloat162_rn(r0, r1);
    h = *reinterpret_cast<uint32_t*>(&hp);
    l = *reinterpret_cast<uint32_t*>(&lp);
}
__device__ __forceinline__ float sigmoidf_(float x) { return 1.0f / (1.0f + expf(-x)); }

// ---------------- kernel 1: gathers + qWh = emb_ctxt[idx] @ W_h + attn_b ----
__global__ void setup_kernel(const int* __restrict__ fc, const int* __restrict__ ft,
                             const float* __restrict__ emb_c, const float* __restrict__ emb_t,
                             const float* __restrict__ attn_W, const float* __restrict__ attn_b)
{
    __shared__ float q[HH];
    int b = blockIdx.x, tid = threadIdx.x;
    int ci = fc[b], ti = ft[b];
    q[tid] = emb_c[ci*HH + tid];
    g_embT[b*HH + tid] = emb_t[ti*HH + tid];
    __syncthreads();
    float acc = attn_b[tid];
#pragma unroll 8
    for (int k = 0; k < HH; k++) acc += q[k] * attn_W[k*HH + tid];
    g_qWh[b*HH + tid] = acc;
}

// ---------------- kernel 1b: W_e transpose + bf16 hi/lo split ----------------
__global__ void prep_W(const float* __restrict__ attn_W)
{
    const float* We = attn_W + HH*HH;                  // [k=512][n=256]
    int idx = blockIdx.x * 256 + threadIdx.x;          // 131072
    int k = idx >> 8, n = idx & 255;
    float x = We[k*HH + n];
    __nv_bfloat16 hi = __float2bfloat16(x);
    __nv_bfloat16 lo = __float2bfloat16(x - __bfloat162float(hi));
    g_Wb_hi[n*FF + k] = hi;
    g_Wb_lo[n*FF + k] = lo;
}

// ---------------- kernel 2: mma.sync bf16-split scores GEMM ----------------
// Per CTA: 128 s-rows x FULL 256 h-cols x K=512 (E read once).
// 512 threads, 16 warps (4m x 4n), warp tile 32x64.
// 3 MMAs per product (hi*hi, hi*lo, lo*hi), fp32 accum.
#define STAGE   49152
#define A_HI    0
#define A_LO    8192
#define B_HI    16384
#define B_LO    32768
#define SM_QW   (2*STAGE)
#define SM_V    (SM_QW + 1024)
#define SM_RED  (SM_V + 1024)
#define SMEM_SC (SM_RED + 2048)

__global__ void __launch_bounds__(512, 1)
scores_mma(const float* __restrict__ E, const float* __restrict__ v)
{
    extern __shared__ char sm[];
    const uint32_t smb = smem_u32(sm);
    const int tid  = threadIdx.x;
    const int lane = tid & 31, warp = tid >> 5;
    const int wm = warp >> 2, wn = warp & 3;       // 4 x 4 warp grid
    const int s0 = blockIdx.x * 128;
    const int b  = blockIdx.y;

    float* sq = (float*)(sm + SM_QW);
    float* sv = (float*)(sm + SM_V);
    if (tid < 256) {
        sq[tid] = g_qWh[b*HH + tid];
        sv[tid] = v[tid];
    }

    // A producer mapping: 1 unit/thread = 8 fp32 (row = tid>>2, seg = tid&3)
    const int seg  = tid & 3;
    const int row0 = tid >> 2;          // 0..127
    const float* Ap = E + ((long)(b*SS + s0 + row0))*FF + seg*8;

    float acc[2][8][4];
#pragma unroll
    for (int mt = 0; mt < 2; mt++)
#pragma unroll
        for (int nt = 0; nt < 8; nt++)
#pragma unroll
            for (int e = 0; e < 4; e++) acc[mt][nt][e] = 0.0f;

    // ---- prologue: produce chunk 0 into stage 0 ----
    {
        char* stp = sm;
#pragma unroll
        for (int j = 0; j < 2; j++) {
            int idx = tid + 512*j;
            int br = idx >> 2, bc = idx & 3;     // br 0..255
            uint32_t d = swoff(br, bc);
            long so = (long)br*FF + bc*8;
            cp_async16(stp + B_HI + d, g_Wb_hi + so);
            cp_async16(stp + B_LO + d, g_Wb_lo + so);
        }
        CP_COMMIT();
        float4 f0 = *(const float4*)(Ap);
        float4 f1 = *(const float4*)(Ap + 4);
        uint32_t H[4], L[4];
        split2(f0.x, f0.y, H[0], L[0]); split2(f0.z, f0.w, H[1], L[1]);
        split2(f1.x, f1.y, H[2], L[2]); split2(f1.z, f1.w, H[3], L[3]);
        uint32_t d0 = swoff(row0, seg);
        *(uint4*)(stp + A_HI + d0) = make_uint4(H[0], H[1], H[2], H[3]);
        *(uint4*)(stp + A_LO + d0) = make_uint4(L[0], L[1], L[2], L[3]);
        CP_WAIT0();
        __syncthreads();
    }

    for (int c = 0; c < 16; c++) {
        const int cur = c & 1;
        char* stn = sm + (cur ^ 1)*STAGE;
        const uint32_t stcb = smb + cur*STAGE;
        float4 f0, f1;
        if (c < 15) {
            const int k1 = (c + 1)*32;
#pragma unroll
            for (int j = 0; j < 2; j++) {
                int idx = tid + 512*j;
                int br = idx >> 2, bc = idx & 3;
                uint32_t d = swoff(br, bc);
                long so = (long)br*FF + k1 + bc*8;
                cp_async16(stn + B_HI + d, g_Wb_hi + so);
                cp_async16(stn + B_LO + d, g_Wb_lo + so);
            }
            CP_COMMIT();
            f0 = *(const float4*)(Ap + k1);
            f1 = *(const float4*)(Ap + k1 + 4);
        }

        // ---- MMAs on stage cur (2 k16-steps) ----
#pragma unroll
        for (int ks = 0; ks < 2; ks++) {
            uint32_t ah[2][4], al[2][4];
#pragma unroll
            for (int mt = 0; mt < 2; mt++) {
                int r   = wm*32 + mt*16 + (lane & 15);
                int c16 = ks*2 + (lane >> 4);
                uint32_t o = swoff(r, c16);
                ldsm_x4(ah[mt], stcb + A_HI + o);
                ldsm_x4(al[mt], stcb + A_LO + o);
            }
#pragma unroll
            for (int h2 = 0; h2 < 2; h2++) {
                uint32_t bh[4][2], bl[4][2];
#pragma unroll
                for (int np = 0; np < 2; np++) {
                    int nr  = wn*64 + (h2*2 + np)*16 + ((lane >> 4) << 3) + (lane & 7);
                    int c16 = ks*2 + ((lane >> 3) & 1);
                    uint32_t o = swoff(nr, c16);
                    uint32_t r4[4];
                    ldsm_x4(r4, stcb + B_HI + o);
                    bh[np*2][0] = r4[0]; bh[np*2][1] = r4[1];
                    bh[np*2+1][0] = r4[2]; bh[np*2+1][1] = r4[3];
                    ldsm_x4(r4, stcb + B_LO + o);
                    bl[np*2][0] = r4[0]; bl[np*2][1] = r4[1];
                    bl[np*2+1][0] = r4[2]; bl[np*2+1][1] = r4[3];
                }
#pragma unroll
                for (int mt = 0; mt < 2; mt++)
#pragma unroll
                    for (int nt = 0; nt < 4; nt++)
                        mma_bf16(acc[mt][h2*4+nt], ah[mt], bh[nt]);
#pragma unroll
                for (int mt = 0; mt < 2; mt++)
#pragma unroll
                    for (int nt = 0; nt < 4; nt++)
                        mma_bf16(acc[mt][h2*4+nt], ah[mt], bl[nt]);
#pragma unroll
                for (int mt = 0; mt < 2; mt++)
#pragma unroll
                    for (int nt = 0; nt < 4; nt++)
                        mma_bf16(acc[mt][h2*4+nt], al[mt], bh[nt]);
            }
        }

        if (c < 15) {
            uint32_t H[4], L[4];
            split2(f0.x, f0.y, H[0], L[0]); split2(f0.z, f0.w, H[1], L[1]);
            split2(f1.x, f1.y, H[2], L[2]); split2(f1.z, f1.w, H[3], L[3]);
            uint32_t d0 = swoff(row0, seg);
            *(uint4*)(stn + A_HI + d0) = make_uint4(H[0], H[1], H[2], H[3]);
            *(uint4*)(stn + A_LO + d0) = make_uint4(L[0], L[1], L[2], L[3]);
            CP_WAIT0();
        }
        __syncthreads();
    }

    // ---- epilogue: +qWh, tanh, dot v over full N=256 ----
    float* red = (float*)(sm + SM_RED);   // [128 rows][4 n-warp groups]
#pragma unroll
    for (int mt = 0; mt < 2; mt++) {
        float pA = 0.0f, pB = 0.0f;
#pragma unroll
        for (int nt = 0; nt < 8; nt++) {
            int h0 = wn*64 + nt*8 + (lane & 3)*2;
            float q0 = sq[h0], q1 = sq[h0 + 1];
            float v0 = sv[h0], v1 = sv[h0 + 1];
            pA += v0*tanhf(acc[mt][nt][0] + q0) + v1*tanhf(acc[mt][nt][1] + q1);
            pB += v0*tanhf(acc[mt][nt][2] + q0) + v1*tanhf(acc[mt][nt][3] + q1);
        }
        pA += __shfl_xor_sync(0xffffffffu, pA, 1);
        pA += __shfl_xor_sync(0xffffffffu, pA, 2);
        pB += __shfl_xor_sync(0xffffffffu, pB, 1);
        pB += __shfl_xor_sync(0xffffffffu, pB, 2);
        if ((lane & 3) == 0) {
            int r = wm*32 + mt*16 + (lane >> 2);
            red[r*4 + wn]       = pA;
            red[(r + 8)*4 + wn] = pB;
        }
    }
    __syncthreads();
    if (tid < 128) {
        float s = red[tid*4] + red[tid*4+1] + red[tid*4+2] + red[tid*4+3];
        g_spart[(long)b*SS + s0 + tid] = s;
    }
}

// ---------------- kernel 3: softmax -> g_scores ----------------
__global__ void softmax_kernel()
{
    __shared__ float red[32];
    const int b = blockIdx.x, tid = threadIdx.x;
    float4 xv = *(const float4*)(g_spart + (long)b*SS + tid*4);
    const unsigned lane = tid & 31, w = tid >> 5;

    float mx = fmaxf(fmaxf(xv.x, xv.y), fmaxf(xv.z, xv.w));
#pragma unroll
    for (int o = 16; o; o >>= 1) mx = fmaxf(mx, __shfl_xor_sync(0xffffffffu, mx, o));
    if (!lane) red[w] = mx;
    __syncthreads();
    if (tid < 32) {
        float t = red[tid];
#pragma unroll
        for (int o = 16; o; o >>= 1) t = fmaxf(t, __shfl_xor_sync(0xffffffffu, t, o));
        if (!tid) red[0] = t;
    }
    __syncthreads();
    const float mm = red[0];
    __syncthreads();

    float4 ev = make_float4(expf(xv.x - mm), expf(xv.y - mm),
                            expf(xv.z - mm), expf(xv.w - mm));
    float s = ev.x + ev.y + ev.z + ev.w;
#pragma unroll
    for (int o = 16; o; o >>= 1) s += __shfl_xor_sync(0xffffffffu, s, o);
    if (!lane) red[w] = s;
    __syncthreads();
    if (tid < 32) {
        float t = red[tid];
#pragma unroll
        for (int o = 16; o; o >>= 1) t += __shfl_xor_sync(0xffffffffu, t, o);
        if (!tid) red[0] = t;
    }
    __syncthreads();
    const float inv = 1.0f / red[0];
    ev.x *= inv; ev.y *= inv; ev.z *= inv; ev.w *= inv;
    *(float4*)(g_scores + b*SS + tid*4) = ev;
}

// ---------------- kernel 4: context partials: part[c][b][f] ----------------
__global__ void ctx_kernel(const float* __restrict__ E)
{
    __shared__ float sa[SS / NCHUNK];
    const int c = blockIdx.x, b = blockIdx.y, tid = threadIdx.x; // 128 threads
    const int s0 = c * (SS / NCHUNK);
    sa[tid]       = g_scores[b*SS + s0 + tid];
    sa[tid + 128] = g_scores[b*SS + s0 + tid + 128];
    __syncthreads();

    float4 acc = make_float4(0.f, 0.f, 0.f, 0.f);
    const float* base = E + (long)(b*SS + s0) * FF + tid*4;
#pragma unroll 8
    for (int s = 0; s < SS / NCHUNK; s++) {
        const float a = sa[s];
        const float4 e = *(const float4*)(base + (long)s * FF);
        acc.x += a*e.x; acc.y += a*e.y; acc.z += a*e.z; acc.w += a*e.w;
    }
    *(float4*)(&g_part[(long)(c*BB + b)*FF + tid*4]) = acc;
}

// ---------------- kernel 5: reduce + GRU + output projection ----------------
__global__ void gru_kernel(const float* __restrict__ w_ih, const float* __restrict__ b_ih,
                           const float* __restrict__ b_hh, const float* __restrict__ out_W,
                           const float* __restrict__ out_b, float* __restrict__ out,
                           int out_size)
{
    __shared__ float x[3*HH];
    __shared__ float g[3*HH];
    __shared__ float h[HH];
    const int b = blockIdx.x, tid = threadIdx.x; // 256 threads

#pragma unroll
    for (int r = 0; r < 2; r++) {
        const int f = tid + r*256;
        float acc = 0.0f;
#pragma unroll
        for (int c = 0; c < NCHUNK; c++) acc += g_part[(long)(c*BB + b)*FF + f];
        x[HH + f] = acc;
    }
    x[tid] = g_embT[b*HH + tid];
    __syncthreads();

#pragma unroll
    for (int r = 0; r < 3; r++) {
        const int jj = tid + r*256;
        float acc = b_ih[jj];
#pragma unroll 8
        for (int k = 0; k < 3*HH; k++) acc += x[k] * w_ih[k*(3*HH) + jj];
        g[jj] = acc;
    }
    __syncthreads();

    {
        const int j = tid;
        const float rg = sigmoidf_(g[j]        + b_hh[j]);
        const float zg = sigmoidf_(g[HH + j]   + b_hh[HH + j]);
        const float ng = tanhf   (g[2*HH + j]  + rg * b_hh[2*HH + j]);
        const float hv = (1.0f - zg) * ng;
        h[j] = hv;
        const int ho = BB*OUTD + b*HH + j;
        if (ho < out_size) out[ho] = hv;
    }
    __syncthreads();

    if (tid < OUTD) {
        float acc = out_b[tid];
#pragma unroll 8
        for (int k = 0; k < HH; k++) acc += h[k] * out_W[k*OUTD + tid];
        out[b*OUTD + tid] = acc;
    }
}

// ---------------- launch ----------------
extern "C" void kernel_launch(void* const* d_in, const int* in_sizes, int n_in,
                              void* d_out, int out_size)
{
    const int*   fc     = (const int*)  d_in[0];   // fut_ctxt (B,1)
    const int*   ft     = (const int*)  d_in[1];   // fut_temp (B,1)
    const float* E      = (const float*)d_in[2];   // encoder_outputs (B,S,2H)
    const float* emb_c  = (const float*)d_in[3];   // emb_ctxt (1000,H)
    const float* emb_t  = (const float*)d_in[4];   // emb_temp (1000,H)
    const float* attn_W = (const float*)d_in[5];   // (3H,H)
    const float* attn_b = (const float*)d_in[6];   // (H,)
    const float* v      = (const float*)d_in[7];   // (H,)
    const float* w_ih   = (const float*)d_in[8];   // (3H,3H)
    // d_in[9] = w_hh: unused since h0 == 0 (gh = b_hh exactly)
    const float* b_ih   = (const float*)d_in[10];  // (3H,)
    const float* b_hh   = (const float*)d_in[11];  // (3H,)
    const float* out_W  = (const float*)d_in[12];  // (H,OUT)
    const float* out_b  = (const float*)d_in[13];  // (OUT,)
    float* out = (float*)d_out;

    cudaFuncSetAttribute(scores_mma, cudaFuncAttributeMaxDynamicSharedMemorySize,
                         SMEM_SC);

    setup_kernel<<<BB, HH>>>(fc, ft, emb_c, emb_t, attn_W, attn_b);
    prep_W<<<512, 256>>>(attn_W);
    scores_mma<<<dim3(SS/128, BB), 512, SMEM_SC>>>(E, v);
    softmax_kernel<<<BB, 1024>>>();
    ctx_kernel<<<dim3(NCHUNK, BB), 128>>>(E);
    gru_kernel<<<BB, 256>>>(w_ih, b_ih, b_hh, out_W, out_b, out, out_size);
}

// round 9
// speedup vs baseline: 2.6377x; 1.3615x over previous
#include <cuda_runtime.h>
#include <cuda_fp16.h>
#include <cstdint>

#define BB   64
#define SS   4096
#define HH   256
#define FF   512      // 2*H
#define OUTD 24
#define NCHUNK 16     // s-chunks for context partials

// ---------------- scratch (static device globals; no allocs) ----------------
__device__ __align__(16) float g_qWh[BB*HH];      // hidden_q @ W_h + attn_b
__device__ __align__(16) float g_embT[BB*HH];     // gathered emb_temp
__device__ __align__(16) float g_scores[BB*SS];   // attn weights (post-softmax)
__device__ __align__(16) float g_spart[BB*SS];    // pre-softmax scores
__device__ __align__(16) float g_part[NCHUNK*BB*FF]; // context partial sums
__device__ __align__(16) __half g_Wh[HH*FF];      // W_e^T fp16 [n=256][k=512]

// ---------------- helpers ----------------
__device__ __forceinline__ uint32_t smem_u32(const void* p) {
    uint32_t a;
    asm("{ .reg .u64 t; cvta.to.shared.u64 t, %1; cvt.u32.u64 %0, t; }"
        : "=r"(a) : "l"(p));
    return a;
}
__device__ __forceinline__ void cp_async16(void* sm, const void* g) {
    unsigned s = (unsigned)__cvta_generic_to_shared(sm);
    asm volatile("cp.async.cg.shared.global [%0], [%1], 16;" :: "r"(s), "l"(g));
}
#define CP_COMMIT() asm volatile("cp.async.commit_group;")
#define CP_WAIT0()  asm volatile("cp.async.wait_group 0;")

__device__ __forceinline__ void ldsm_x4(uint32_t* r, uint32_t addr) {
    asm volatile("ldmatrix.sync.aligned.m8n8.x4.shared.b16 {%0,%1,%2,%3}, [%4];"
        : "=r"(r[0]), "=r"(r[1]), "=r"(r[2]), "=r"(r[3]) : "r"(addr));
}
__device__ __forceinline__ void mma_fp16(float* c, const uint32_t* a, const uint32_t* b) {
    asm volatile("mma.sync.aligned.m16n8k16.row.col.f32.f16.f16.f32 "
        "{%0,%1,%2,%3}, {%4,%5,%6,%7}, {%8,%9}, {%0,%1,%2,%3};"
        : "+f"(c[0]), "+f"(c[1]), "+f"(c[2]), "+f"(c[3])
        : "r"(a[0]), "r"(a[1]), "r"(a[2]), "r"(a[3]), "r"(b[0]), "r"(b[1]));
}
// 128B-row swizzle: 16B chunk c (0..7) of row r
__device__ __forceinline__ uint32_t sw128(int r, int c) {
    return (uint32_t)(r*128 + ((c ^ (r & 7)) << 4));
}
__device__ __forceinline__ float sigmoidf_(float x) { return 1.0f / (1.0f + expf(-x)); }

// ---------------- kernel 1: gathers + qWh = emb_ctxt[idx] @ W_h + attn_b ----
__global__ void setup_kernel(const int* __restrict__ fc, const int* __restrict__ ft,
                             const float* __restrict__ emb_c, const float* __restrict__ emb_t,
                             const float* __restrict__ attn_W, const float* __restrict__ attn_b)
{
    __shared__ float q[HH];
    int b = blockIdx.x, tid = threadIdx.x;
    int ci = fc[b], ti = ft[b];
    q[tid] = emb_c[ci*HH + tid];
    g_embT[b*HH + tid] = emb_t[ti*HH + tid];
    __syncthreads();
    float acc = attn_b[tid];
#pragma unroll 8
    for (int k = 0; k < HH; k++) acc += q[k] * attn_W[k*HH + tid];
    g_qWh[b*HH + tid] = acc;
}

// ---------------- kernel 1b: W_e transpose + fp16 convert ----------------
__global__ void prep_W(const float* __restrict__ attn_W)
{
    const float* We = attn_W + HH*HH;                  // [k=512][n=256]
    int idx = blockIdx.x * 256 + threadIdx.x;          // 131072
    int k = idx >> 8, n = idx & 255;
    g_Wh[n*FF + k] = __float2half_rn(We[k*HH + n]);
}

// ---------------- kernel 2: fp16 mma.sync scores GEMM ----------------
// Per CTA: 128 s-rows x 256 h-cols x K=512.  512 threads, 16 warps (4m x 4n),
// warp tile 32x64. Single fp16 MMA per product, fp32 accum.
// K pipelined in 8 chunks of 64, double-buffered.
#define STAGE   49152                // A 16KB + B 32KB
#define A_OFF   0
#define B_OFF   16384
#define SM_QW   (2*STAGE)
#define SM_V    (SM_QW + 1024)
#define SM_RED  (SM_V + 1024)
#define SMEM_SC (SM_RED + 2048)

__global__ void __launch_bounds__(512, 1)
scores_mma(const float* __restrict__ E, const float* __restrict__ v)
{
    extern __shared__ char sm[];
    const uint32_t smb = smem_u32(sm);
    const int tid  = threadIdx.x;
    const int lane = tid & 31, warp = tid >> 5;
    const int wm = warp >> 2, wn = warp & 3;       // 4 x 4 warp grid
    const int s0 = blockIdx.x * 128;
    const int b  = blockIdx.y;

    float* sq = (float*)(sm + SM_QW);
    float* sv = (float*)(sm + SM_V);
    if (tid < 256) {
        sq[tid] = g_qWh[b*HH + tid];
        sv[tid] = v[tid];
    }

    // A producer mapping: row0 = tid>>2 (0..127), seg = tid&3 (16 k each)
    const int seg  = tid & 3;
    const int row0 = tid >> 2;
    const float* Ap = E + ((long)(b*SS + s0 + row0))*FF + seg*16;

    float acc[2][8][4];
#pragma unroll
    for (int mt = 0; mt < 2; mt++)
#pragma unroll
        for (int nt = 0; nt < 8; nt++)
#pragma unroll
            for (int e = 0; e < 4; e++) acc[mt][nt][e] = 0.0f;

    // ---- producer lambda-ish macro: load+convert A, cp.async B for chunk k0 into stage st ----
#define PRODUCE(stp, k0)                                                         \
    do {                                                                         \
        _Pragma("unroll")                                                        \
        for (int j = 0; j < 4; j++) {                                            \
            int idx = tid + 512*j;                                               \
            int br = idx >> 3, bc = idx & 7;                                     \
            cp_async16((stp) + B_OFF + sw128(br, bc), g_Wh + (long)br*FF + (k0) + bc*8); \
        }                                                                        \
        CP_COMMIT();                                                             \
        float4 f0 = *(const float4*)(Ap + (k0));                                 \
        float4 f1 = *(const float4*)(Ap + (k0) + 4);                             \
        float4 f2 = *(const float4*)(Ap + (k0) + 8);                             \
        float4 f3 = *(const float4*)(Ap + (k0) + 12);                            \
        __half2 h0 = __floats2half2_rn(f0.x, f0.y);                              \
        __half2 h1 = __floats2half2_rn(f0.z, f0.w);                              \
        __half2 h2 = __floats2half2_rn(f1.x, f1.y);                              \
        __half2 h3 = __floats2half2_rn(f1.z, f1.w);                              \
        __half2 h4 = __floats2half2_rn(f2.x, f2.y);                              \
        __half2 h5 = __floats2half2_rn(f2.z, f2.w);                              \
        __half2 h6 = __floats2half2_rn(f3.x, f3.y);                              \
        __half2 h7 = __floats2half2_rn(f3.z, f3.w);                              \
        uint32_t d0 = sw128(row0, seg*2);                                        \
        uint32_t d1 = sw128(row0, seg*2 + 1);                                    \
        *(uint4*)((stp) + A_OFF + d0) = make_uint4(                              \
            *(uint32_t*)&h0, *(uint32_t*)&h1, *(uint32_t*)&h2, *(uint32_t*)&h3); \
        *(uint4*)((stp) + A_OFF + d1) = make_uint4(                              \
            *(uint32_t*)&h4, *(uint32_t*)&h5, *(uint32_t*)&h6, *(uint32_t*)&h7); \
    } while (0)

    // ---- prologue: chunk 0 into stage 0 ----
    PRODUCE(sm, 0);
    CP_WAIT0();
    __syncthreads();

    for (int c = 0; c < 8; c++) {
        const int cur = c & 1;
        char* stn = sm + (cur ^ 1)*STAGE;
        const uint32_t stcb = smb + cur*STAGE;
        if (c < 7) PRODUCE(stn, (c + 1)*64);

        // ---- MMAs on stage cur (4 k16-steps) ----
#pragma unroll
        for (int ks = 0; ks < 4; ks++) {
            uint32_t af[2][4];
#pragma unroll
            for (int mt = 0; mt < 2; mt++) {
                int r = wm*32 + mt*16 + (lane & 15);
                ldsm_x4(af[mt], stcb + A_OFF + sw128(r, ks*2 + (lane >> 4)));
            }
#pragma unroll
            for (int nb = 0; nb < 4; nb++) {
                int nr = wn*64 + nb*16 + ((lane >> 4) << 3) + (lane & 7);
                int cc = ks*2 + ((lane >> 3) & 1);
                uint32_t r4[4];
                ldsm_x4(r4, stcb + B_OFF + sw128(nr, cc));
                uint32_t b0[2] = { r4[0], r4[1] };
                uint32_t b1[2] = { r4[2], r4[3] };
#pragma unroll
                for (int mt = 0; mt < 2; mt++) {
                    mma_fp16(acc[mt][nb*2],     af[mt], b0);
                    mma_fp16(acc[mt][nb*2 + 1], af[mt], b1);
                }
            }
        }

        if (c < 7) CP_WAIT0();
        __syncthreads();
    }

    // ---- epilogue: +qWh, tanh, dot v over full N=256 ----
    float* red = (float*)(sm + SM_RED);   // [128 rows][4 n-warp groups]
#pragma unroll
    for (int mt = 0; mt < 2; mt++) {
        float pA = 0.0f, pB = 0.0f;
#pragma unroll
        for (int nt = 0; nt < 8; nt++) {
            int h0 = wn*64 + nt*8 + (lane & 3)*2;
            float q0 = sq[h0], q1 = sq[h0 + 1];
            float v0 = sv[h0], v1 = sv[h0 + 1];
            pA += v0*tanhf(acc[mt][nt][0] + q0) + v1*tanhf(acc[mt][nt][1] + q1);
            pB += v0*tanhf(acc[mt][nt][2] + q0) + v1*tanhf(acc[mt][nt][3] + q1);
        }
        pA += __shfl_xor_sync(0xffffffffu, pA, 1);
        pA += __shfl_xor_sync(0xffffffffu, pA, 2);
        pB += __shfl_xor_sync(0xffffffffu, pB, 1);
        pB += __shfl_xor_sync(0xffffffffu, pB, 2);
        if ((lane & 3) == 0) {
            int r = wm*32 + mt*16 + (lane >> 2);
            red[r*4 + wn]       = pA;
            red[(r + 8)*4 + wn] = pB;
        }
    }
    __syncthreads();
    if (tid < 128) {
        float s = red[tid*4] + red[tid*4+1] + red[tid*4+2] + red[tid*4+3];
        g_spart[(long)b*SS + s0 + tid] = s;
    }
}

// ---------------- kernel 3: softmax -> g_scores ----------------
__global__ void softmax_kernel()
{
    __shared__ float red[32];
    const int b = blockIdx.x, tid = threadIdx.x;
    float4 xv = *(const float4*)(g_spart + (long)b*SS + tid*4);
    const unsigned lane = tid & 31, w = tid >> 5;

    float mx = fmaxf(fmaxf(xv.x, xv.y), fmaxf(xv.z, xv.w));
#pragma unroll
    for (int o = 16; o; o >>= 1) mx = fmaxf(mx, __shfl_xor_sync(0xffffffffu, mx, o));
    if (!lane) red[w] = mx;
    __syncthreads();
    if (tid < 32) {
        float t = red[tid];
#pragma unroll
        for (int o = 16; o; o >>= 1) t = fmaxf(t, __shfl_xor_sync(0xffffffffu, t, o));
        if (!tid) red[0] = t;
    }
    __syncthreads();
    const float mm = red[0];
    __syncthreads();

    float4 ev = make_float4(expf(xv.x - mm), expf(xv.y - mm),
                            expf(xv.z - mm), expf(xv.w - mm));
    float s = ev.x + ev.y + ev.z + ev.w;
#pragma unroll
    for (int o = 16; o; o >>= 1) s += __shfl_xor_sync(0xffffffffu, s, o);
    if (!lane) red[w] = s;
    __syncthreads();
    if (tid < 32) {
        float t = red[tid];
#pragma unroll
        for (int o = 16; o; o >>= 1) t += __shfl_xor_sync(0xffffffffu, t, o);
        if (!tid) red[0] = t;
    }
    __syncthreads();
    const float inv = 1.0f / red[0];
    ev.x *= inv; ev.y *= inv; ev.z *= inv; ev.w *= inv;
    *(float4*)(g_scores + b*SS + tid*4) = ev;
}

// ---------------- kernel 4: context partials: part[c][b][f] ----------------
__global__ void ctx_kernel(const float* __restrict__ E)
{
    __shared__ float sa[SS / NCHUNK];
    const int c = blockIdx.x, b = blockIdx.y, tid = threadIdx.x; // 128 threads
    const int s0 = c * (SS / NCHUNK);
    sa[tid]       = g_scores[b*SS + s0 + tid];
    sa[tid + 128] = g_scores[b*SS + s0 + tid + 128];
    __syncthreads();

    float4 acc = make_float4(0.f, 0.f, 0.f, 0.f);
    const float* base = E + (long)(b*SS + s0) * FF + tid*4;
#pragma unroll 8
    for (int s = 0; s < SS / NCHUNK; s++) {
        const float a = sa[s];
        const float4 e = *(const float4*)(base + (long)s * FF);
        acc.x += a*e.x; acc.y += a*e.y; acc.z += a*e.z; acc.w += a*e.w;
    }
    *(float4*)(&g_part[(long)(c*BB + b)*FF + tid*4]) = acc;
}

// ---------------- kernel 5: reduce + GRU + output projection ----------------
__global__ void gru_kernel(const float* __restrict__ w_ih, const float* __restrict__ b_ih,
                           const float* __restrict__ b_hh, const float* __restrict__ out_W,
                           const float* __restrict__ out_b, float* __restrict__ out,
                           int out_size)
{
    __shared__ float x[3*HH];
    __shared__ float g[3*HH];
    __shared__ float h[HH];
    const int b = blockIdx.x, tid = threadIdx.x; // 256 threads

#pragma unroll
    for (int r = 0; r < 2; r++) {
        const int f = tid + r*256;
        float acc = 0.0f;
#pragma unroll
        for (int c = 0; c < NCHUNK; c++) acc += g_part[(long)(c*BB + b)*FF + f];
        x[HH + f] = acc;
    }
    x[tid] = g_embT[b*HH + tid];
    __syncthreads();

#pragma unroll
    for (int r = 0; r < 3; r++) {
        const int jj = tid + r*256;
        float acc = b_ih[jj];
#pragma unroll 8
        for (int k = 0; k < 3*HH; k++) acc += x[k] * w_ih[k*(3*HH) + jj];
        g[jj] = acc;
    }
    __syncthreads();

    {
        const int j = tid;
        const float rg = sigmoidf_(g[j]        + b_hh[j]);
        const float zg = sigmoidf_(g[HH + j]   + b_hh[HH + j]);
        const float ng = tanhf   (g[2*HH + j]  + rg * b_hh[2*HH + j]);
        const float hv = (1.0f - zg) * ng;
        h[j] = hv;
        const int ho = BB*OUTD + b*HH + j;
        if (ho < out_size) out[ho] = hv;
    }
    __syncthreads();

    if (tid < OUTD) {
        float acc = out_b[tid];
#pragma unroll 8
        for (int k = 0; k < HH; k++) acc += h[k] * out_W[k*OUTD + tid];
        out[b*OUTD + tid] = acc;
    }
}

// ---------------- launch ----------------
extern "C" void kernel_launch(void* const* d_in, const int* in_sizes, int n_in,
                              void* d_out, int out_size)
{
    const int*   fc     = (const int*)  d_in[0];   // fut_ctxt (B,1)
    const int*   ft     = (const int*)  d_in[1];   // fut_temp (B,1)
    const float* E      = (const float*)d_in[2];   // encoder_outputs (B,S,2H)
    const float* emb_c  = (const float*)d_in[3];   // emb_ctxt (1000,H)
    const float* emb_t  = (const float*)d_in[4];   // emb_temp (1000,H)
    const float* attn_W = (const float*)d_in[5];   // (3H,H)
    const float* attn_b = (const float*)d_in[6];   // (H,)
    const float* v      = (const float*)d_in[7];   // (H,)
    const float* w_ih   = (const float*)d_in[8];   // (3H,3H)
    // d_in[9] = w_hh: unused since h0 == 0 (gh = b_hh exactly)
    const float* b_ih   = (const float*)d_in[10];  // (3H,)
    const float* b_hh   = (const float*)d_in[11];  // (3H,)
    const float* out_W  = (const float*)d_in[12];  // (H,OUT)
    const float* out_b  = (const float*)d_in[13];  // (OUT,)
    float* out = (float*)d_out;

    cudaFuncSetAttribute(scores_mma, cudaFuncAttributeMaxDynamicSharedMemorySize,
                         SMEM_SC);

    setup_kernel<<<BB, HH>>>(fc, ft, emb_c, emb_t, attn_W, attn_b);
    prep_W<<<512, 256>>>(attn_W);
    scores_mma<<<dim3(SS/128, BB), 512, SMEM_SC>>>(E, v);
    softmax_kernel<<<BB, 1024>>>();
    ctx_kernel<<<dim3(NCHUNK, BB), 128>>>(E);
    gru_kernel<<<BB, 256>>>(w_ih, b_ih, b_hh, out_W, out_b, out, out_size);
}

// round 10
// speedup vs baseline: 2.9117x; 1.1039x over previous
#include <cuda_runtime.h>
#include <cuda_fp16.h>
#include <cstdint>

#define BB   64
#define SS   4096
#define HH   256
#define FF   512      // 2*H
#define OUTD 24
#define NCHUNK 16     // s-chunks for context partials

// ---------------- scratch (static device globals; no allocs) ----------------
__device__ __align__(16) float g_qWh[BB*HH];      // hidden_q @ W_h + attn_b
__device__ __align__(16) float g_embT[BB*HH];     // gathered emb_temp
__device__ __align__(16) float g_scores[BB*SS];   // attn weights (post-softmax)
__device__ __align__(16) float g_spart[BB*SS];    // pre-softmax scores
__device__ __align__(16) float g_part[NCHUNK*BB*FF]; // context partial sums
__device__ __align__(16) __half g_Wh[HH*FF];      // W_e^T fp16 [n=256][k=512]

// ---------------- helpers ----------------
__device__ __forceinline__ uint32_t smem_u32(const void* p) {
    uint32_t a;
    asm("{ .reg .u64 t; cvta.to.shared.u64 t, %1; cvt.u32.u64 %0, t; }"
        : "=r"(a) : "l"(p));
    return a;
}
__device__ __forceinline__ void cp_async16(void* sm, const void* g) {
    unsigned s = (unsigned)__cvta_generic_to_shared(sm);
    asm volatile("cp.async.cg.shared.global [%0], [%1], 16;" :: "r"(s), "l"(g));
}
#define CP_COMMIT() asm volatile("cp.async.commit_group;")
#define CP_WAIT0()  asm volatile("cp.async.wait_group 0;")

__device__ __forceinline__ void ldsm_x4(uint32_t* r, uint32_t addr) {
    asm volatile("ldmatrix.sync.aligned.m8n8.x4.shared.b16 {%0,%1,%2,%3}, [%4];"
        : "=r"(r[0]), "=r"(r[1]), "=r"(r[2]), "=r"(r[3]) : "r"(addr));
}
__device__ __forceinline__ void mma_fp16(float* c, const uint32_t* a, const uint32_t* b) {
    asm volatile("mma.sync.aligned.m16n8k16.row.col.f32.f16.f16.f32 "
        "{%0,%1,%2,%3}, {%4,%5,%6,%7}, {%8,%9}, {%0,%1,%2,%3};"
        : "+f"(c[0]), "+f"(c[1]), "+f"(c[2]), "+f"(c[3])
        : "r"(a[0]), "r"(a[1]), "r"(a[2]), "r"(a[3]), "r"(b[0]), "r"(b[1]));
}
// 128B-row swizzle: 16B chunk c (0..7) of row r
__device__ __forceinline__ uint32_t sw128(int r, int c) {
    return (uint32_t)(r*128 + ((c ^ (r & 7)) << 4));
}
__device__ __forceinline__ float sigmoidf_(float x) { return 1.0f / (1.0f + expf(-x)); }

// ---------------- kernel 1: gathers + qWh = emb_ctxt[idx] @ W_h + attn_b ----
__global__ void setup_kernel(const int* __restrict__ fc, const int* __restrict__ ft,
                             const float* __restrict__ emb_c, const float* __restrict__ emb_t,
                             const float* __restrict__ attn_W, const float* __restrict__ attn_b)
{
    __shared__ float q[HH];
    int b = blockIdx.x, tid = threadIdx.x;
    int ci = fc[b], ti = ft[b];
    q[tid] = emb_c[ci*HH + tid];
    g_embT[b*HH + tid] = emb_t[ti*HH + tid];
    __syncthreads();
    float acc = attn_b[tid];
#pragma unroll 8
    for (int k = 0; k < HH; k++) acc += q[k] * attn_W[k*HH + tid];
    g_qWh[b*HH + tid] = acc;
}

// ---------------- kernel 1b: W_e transpose + fp16 convert ----------------
__global__ void prep_W(const float* __restrict__ attn_W)
{
    const float* We = attn_W + HH*HH;                  // [k=512][n=256]
    int idx = blockIdx.x * 256 + threadIdx.x;          // 131072
    int k = idx >> 8, n = idx & 255;
    g_Wh[n*FF + k] = __float2half_rn(We[k*HH + n]);
}

// ---------------- kernel 2: fp16 mma.sync scores GEMM (pipelined) ----------
// Per CTA: 128 s-rows x 256 h-cols x K=512.  512 threads, 16 warps (4m x 4n),
// warp tile 32x64. Single fp16 MMA per product, fp32 accum.
// K pipelined in 8 chunks of 64, double-buffered; producer split so the
// DRAM LDG latency is covered by the MMA phase (LDG issue BEFORE MMAs,
// convert+STS AFTER).
#define STAGE   49152                // A 16KB + B 32KB
#define A_OFF   0
#define B_OFF   16384
#define SM_QW   (2*STAGE)
#define SM_V    (SM_QW + 1024)
#define SM_RED  (SM_V + 1024)
#define SMEM_SC (SM_RED + 2048)

__global__ void __launch_bounds__(512, 1)
scores_mma(const float* __restrict__ E, const float* __restrict__ v)
{
    extern __shared__ char sm[];
    const uint32_t smb = smem_u32(sm);
    const int tid  = threadIdx.x;
    const int lane = tid & 31, warp = tid >> 5;
    const int wm = warp >> 2, wn = warp & 3;       // 4 x 4 warp grid
    const int s0 = blockIdx.x * 128;
    const int b  = blockIdx.y;

    float* sq = (float*)(sm + SM_QW);
    float* sv = (float*)(sm + SM_V);
    if (tid < 256) {
        sq[tid] = g_qWh[b*HH + tid];
        sv[tid] = v[tid];
    }

    // A producer mapping: row0 = tid>>2 (0..127), seg = tid&3 (16 k each)
    const int seg  = tid & 3;
    const int row0 = tid >> 2;
    const float* Ap = E + ((long)(b*SS + s0 + row0))*FF + seg*16;
    const uint32_t dA0 = sw128(row0, seg*2);
    const uint32_t dA1 = sw128(row0, seg*2 + 1);

    float acc[2][8][4];
#pragma unroll
    for (int mt = 0; mt < 2; mt++)
#pragma unroll
        for (int nt = 0; nt < 8; nt++)
#pragma unroll
            for (int e = 0; e < 4; e++) acc[mt][nt][e] = 0.0f;

    // issue cp.async for B chunk (into stage pointer stp)
#define B_FETCH(stp, k0)                                                         \
    do {                                                                         \
        _Pragma("unroll")                                                        \
        for (int j = 0; j < 4; j++) {                                            \
            int idx = tid + 512*j;                                               \
            int br = idx >> 3, bc = idx & 7;                                     \
            cp_async16((stp) + B_OFF + sw128(br, bc),                            \
                       g_Wh + (long)br*FF + (k0) + bc*8);                        \
        }                                                                        \
        CP_COMMIT();                                                             \
    } while (0)

    // convert 16 prefetched floats -> fp16 and store to stage
#define A_STORE(stp, f0, f1, f2, f3)                                             \
    do {                                                                         \
        __half2 h0 = __floats2half2_rn((f0).x, (f0).y);                          \
        __half2 h1 = __floats2half2_rn((f0).z, (f0).w);                          \
        __half2 h2 = __floats2half2_rn((f1).x, (f1).y);                          \
        __half2 h3 = __floats2half2_rn((f1).z, (f1).w);                          \
        __half2 h4 = __floats2half2_rn((f2).x, (f2).y);                          \
        __half2 h5 = __floats2half2_rn((f2).z, (f2).w);                          \
        __half2 h6 = __floats2half2_rn((f3).x, (f3).y);                          \
        __half2 h7 = __floats2half2_rn((f3).z, (f3).w);                          \
        *(uint4*)((stp) + A_OFF + dA0) = make_uint4(                             \
            *(uint32_t*)&h0, *(uint32_t*)&h1, *(uint32_t*)&h2, *(uint32_t*)&h3); \
        *(uint4*)((stp) + A_OFF + dA1) = make_uint4(                             \
            *(uint32_t*)&h4, *(uint32_t*)&h5, *(uint32_t*)&h6, *(uint32_t*)&h7); \
    } while (0)

    // ---- prologue: chunk 0 into stage 0 ----
    {
        B_FETCH(sm, 0);
        float4 f0 = *(const float4*)(Ap);
        float4 f1 = *(const float4*)(Ap + 4);
        float4 f2 = *(const float4*)(Ap + 8);
        float4 f3 = *(const float4*)(Ap + 12);
        A_STORE(sm, f0, f1, f2, f3);
        CP_WAIT0();
        __syncthreads();
    }

    for (int c = 0; c < 8; c++) {
        const int cur = c & 1;
        char* stn = sm + (cur ^ 1)*STAGE;
        const uint32_t stcb = smb + cur*STAGE;

        // ---- prefetch chunk c+1: cp.async B + LDG A into registers ----
        float4 f0, f1, f2, f3;
        if (c < 7) {
            const int k1 = (c + 1)*64;
            B_FETCH(stn, k1);
            f0 = *(const float4*)(Ap + k1);
            f1 = *(const float4*)(Ap + k1 + 4);
            f2 = *(const float4*)(Ap + k1 + 8);
            f3 = *(const float4*)(Ap + k1 + 12);
        }

        // ---- MMAs on stage cur (4 k16-steps) — covers LDG latency ----
#pragma unroll
        for (int ks = 0; ks < 4; ks++) {
            uint32_t af[2][4];
#pragma unroll
            for (int mt = 0; mt < 2; mt++) {
                int r = wm*32 + mt*16 + (lane & 15);
                ldsm_x4(af[mt], stcb + A_OFF + sw128(r, ks*2 + (lane >> 4)));
            }
#pragma unroll
            for (int nb = 0; nb < 4; nb++) {
                int nr = wn*64 + nb*16 + ((lane >> 4) << 3) + (lane & 7);
                int cc = ks*2 + ((lane >> 3) & 1);
                uint32_t r4[4];
                ldsm_x4(r4, stcb + B_OFF + sw128(nr, cc));
                uint32_t b0[2] = { r4[0], r4[1] };
                uint32_t b1[2] = { r4[2], r4[3] };
#pragma unroll
                for (int mt = 0; mt < 2; mt++) {
                    mma_fp16(acc[mt][nb*2],     af[mt], b0);
                    mma_fp16(acc[mt][nb*2 + 1], af[mt], b1);
                }
            }
        }

        // ---- convert + STS chunk c+1 after MMAs ----
        if (c < 7) {
            A_STORE(stn, f0, f1, f2, f3);
            CP_WAIT0();
        }
        __syncthreads();
    }

    // ---- epilogue: +qWh, tanh, dot v over full N=256 ----
    float* red = (float*)(sm + SM_RED);   // [128 rows][4 n-warp groups]
#pragma unroll
    for (int mt = 0; mt < 2; mt++) {
        float pA = 0.0f, pB = 0.0f;
#pragma unroll
        for (int nt = 0; nt < 8; nt++) {
            int h0 = wn*64 + nt*8 + (lane & 3)*2;
            float q0 = sq[h0], q1 = sq[h0 + 1];
            float v0 = sv[h0], v1 = sv[h0 + 1];
            pA += v0*tanhf(acc[mt][nt][0] + q0) + v1*tanhf(acc[mt][nt][1] + q1);
            pB += v0*tanhf(acc[mt][nt][2] + q0) + v1*tanhf(acc[mt][nt][3] + q1);
        }
        pA += __shfl_xor_sync(0xffffffffu, pA, 1);
        pA += __shfl_xor_sync(0xffffffffu, pA, 2);
        pB += __shfl_xor_sync(0xffffffffu, pB, 1);
        pB += __shfl_xor_sync(0xffffffffu, pB, 2);
        if ((lane & 3) == 0) {
            int r = wm*32 + mt*16 + (lane >> 2);
            red[r*4 + wn]       = pA;
            red[(r + 8)*4 + wn] = pB;
        }
    }
    __syncthreads();
    if (tid < 128) {
        float s = red[tid*4] + red[tid*4+1] + red[tid*4+2] + red[tid*4+3];
        g_spart[(long)b*SS + s0 + tid] = s;
    }
}

// ---------------- kernel 3: softmax -> g_scores ----------------
__global__ void softmax_kernel()
{
    __shared__ float red[32];
    const int b = blockIdx.x, tid = threadIdx.x;
    float4 xv = *(const float4*)(g_spart + (long)b*SS + tid*4);
    const unsigned lane = tid & 31, w = tid >> 5;

    float mx = fmaxf(fmaxf(xv.x, xv.y), fmaxf(xv.z, xv.w));
#pragma unroll
    for (int o = 16; o; o >>= 1) mx = fmaxf(mx, __shfl_xor_sync(0xffffffffu, mx, o));
    if (!lane) red[w] = mx;
    __syncthreads();
    if (tid < 32) {
        float t = red[tid];
#pragma unroll
        for (int o = 16; o; o >>= 1) t = fmaxf(t, __shfl_xor_sync(0xffffffffu, t, o));
        if (!tid) red[0] = t;
    }
    __syncthreads();
    const float mm = red[0];
    __syncthreads();

    float4 ev = make_float4(expf(xv.x - mm), expf(xv.y - mm),
                            expf(xv.z - mm), expf(xv.w - mm));
    float s = ev.x + ev.y + ev.z + ev.w;
#pragma unroll
    for (int o = 16; o; o >>= 1) s += __shfl_xor_sync(0xffffffffu, s, o);
    if (!lane) red[w] = s;
    __syncthreads();
    if (tid < 32) {
        float t = red[tid];
#pragma unroll
        for (int o = 16; o; o >>= 1) t += __shfl_xor_sync(0xffffffffu, t, o);
        if (!tid) red[0] = t;
    }
    __syncthreads();
    const float inv = 1.0f / red[0];
    ev.x *= inv; ev.y *= inv; ev.z *= inv; ev.w *= inv;
    *(float4*)(g_scores + b*SS + tid*4) = ev;
}

// ---------------- kernel 4: context partials: part[c][b][f] ----------------
__global__ void ctx_kernel(const float* __restrict__ E)
{
    __shared__ float sa[SS / NCHUNK];
    const int c = blockIdx.x, b = blockIdx.y, tid = threadIdx.x; // 128 threads
    const int s0 = c * (SS / NCHUNK);
    sa[tid]       = g_scores[b*SS + s0 + tid];
    sa[tid + 128] = g_scores[b*SS + s0 + tid + 128];
    __syncthreads();

    float4 acc = make_float4(0.f, 0.f, 0.f, 0.f);
    const float* base = E + (long)(b*SS + s0) * FF + tid*4;
#pragma unroll 8
    for (int s = 0; s < SS / NCHUNK; s++) {
        const float a = sa[s];
        const float4 e = *(const float4*)(base + (long)s * FF);
        acc.x += a*e.x; acc.y += a*e.y; acc.z += a*e.z; acc.w += a*e.w;
    }
    *(float4*)(&g_part[(long)(c*BB + b)*FF + tid*4]) = acc;
}

// ---------------- kernel 5: reduce + GRU + output projection ----------------
__global__ void gru_kernel(const float* __restrict__ w_ih, const float* __restrict__ b_ih,
                           const float* __restrict__ b_hh, const float* __restrict__ out_W,
                           const float* __restrict__ out_b, float* __restrict__ out,
                           int out_size)
{
    __shared__ float x[3*HH];
    __shared__ float g[3*HH];
    __shared__ float h[HH];
    const int b = blockIdx.x, tid = threadIdx.x; // 256 threads

#pragma unroll
    for (int r = 0; r < 2; r++) {
        const int f = tid + r*256;
        float acc = 0.0f;
#pragma unroll
        for (int c = 0; c < NCHUNK; c++) acc += g_part[(long)(c*BB + b)*FF + f];
        x[HH + f] = acc;
    }
    x[tid] = g_embT[b*HH + tid];
    __syncthreads();

#pragma unroll
    for (int r = 0; r < 3; r++) {
        const int jj = tid + r*256;
        float acc = b_ih[jj];
#pragma unroll 8
        for (int k = 0; k < 3*HH; k++) acc += x[k] * w_ih[k*(3*HH) + jj];
        g[jj] = acc;
    }
    __syncthreads();

    {
        const int j = tid;
        const float rg = sigmoidf_(g[j]        + b_hh[j]);
        const float zg = sigmoidf_(g[HH + j]   + b_hh[HH + j]);
        const float ng = tanhf   (g[2*HH + j]  + rg * b_hh[2*HH + j]);
        const float hv = (1.0f - zg) * ng;
        h[j] = hv;
        const int ho = BB*OUTD + b*HH + j;
        if (ho < out_size) out[ho] = hv;
    }
    __syncthreads();

    if (tid < OUTD) {
        float acc = out_b[tid];
#pragma unroll 8
        for (int k = 0; k < HH; k++) acc += h[k] * out_W[k*OUTD + tid];
        out[b*OUTD + tid] = acc;
    }
}

// ---------------- launch ----------------
extern "C" void kernel_launch(void* const* d_in, const int* in_sizes, int n_in,
                              void* d_out, int out_size)
{
    const int*   fc     = (const int*)  d_in[0];   // fut_ctxt (B,1)
    const int*   ft     = (const int*)  d_in[1];   // fut_temp (B,1)
    const float* E      = (const float*)d_in[2];   // encoder_outputs (B,S,2H)
    const float* emb_c  = (const float*)d_in[3];   // emb_ctxt (1000,H)
    const float* emb_t  = (const float*)d_in[4];   // emb_temp (1000,H)
    const float* attn_W = (const float*)d_in[5];   // (3H,H)
    const float* attn_b = (const float*)d_in[6];   // (H,)
    const float* v      = (const float*)d_in[7];   // (H,)
    const float* w_ih   = (const float*)d_in[8];   // (3H,3H)
    // d_in[9] = w_hh: unused since h0 == 0 (gh = b_hh exactly)
    const float* b_ih   = (const float*)d_in[10];  // (3H,)
    const float* b_hh   = (const float*)d_in[11];  // (3H,)
    const float* out_W  = (const float*)d_in[12];  // (H,OUT)
    const float* out_b  = (const float*)d_in[13];  // (OUT,)
    float* out = (float*)d_out;

    cudaFuncSetAttribute(scores_mma, cudaFuncAttributeMaxDynamicSharedMemorySize,
                         SMEM_SC);

    setup_kernel<<<BB, HH>>>(fc, ft, emb_c, emb_t, attn_W, attn_b);
    prep_W<<<512, 256>>>(attn_W);
    scores_mma<<<dim3(SS/128, BB), 512, SMEM_SC>>>(E, v);
    softmax_kernel<<<BB, 1024>>>();
    ctx_kernel<<<dim3(NCHUNK, BB), 128>>>(E);
    gru_kernel<<<BB, 256>>>(w_ih, b_ih, b_hh, out_W, out_b, out, out_size);
}

// round 11
// speedup vs baseline: 2.9379x; 1.0090x over previous
#include <cuda_runtime.h>
#include <cuda_fp16.h>
#include <cstdint>

#define BB   64
#define SS   4096
#define HH   256
#define FF   512      // 2*H
#define OUTD 24
#define NCHUNK 16     // s-chunks for context partials

// ---------------- scratch (static device globals; no allocs) ----------------
__device__ __align__(16) float g_qWh[BB*HH];      // hidden_q @ W_h + attn_b
__device__ __align__(16) float g_embT[BB*HH];     // gathered emb_temp
__device__ __align__(16) float g_scores[BB*SS];   // attn weights (post-softmax)
__device__ __align__(16) float g_spart[BB*SS];    // pre-softmax scores
__device__ __align__(16) float g_part[NCHUNK*BB*FF]; // context partial sums
__device__ __align__(16) __half g_Wh[HH*FF];      // W_e^T fp16 [n=256][k=512]

// ---------------- helpers ----------------
__device__ __forceinline__ uint32_t smem_u32(const void* p) {
    uint32_t a;
    asm("{ .reg .u64 t; cvta.to.shared.u64 t, %1; cvt.u32.u64 %0, t; }"
        : "=r"(a) : "l"(p));
    return a;
}
__device__ __forceinline__ void cp_async16(void* sm, const void* g) {
    unsigned s = (unsigned)__cvta_generic_to_shared(sm);
    asm volatile("cp.async.cg.shared.global [%0], [%1], 16;" :: "r"(s), "l"(g));
}
#define CP_COMMIT() asm volatile("cp.async.commit_group;")
#define CP_WAIT0()  asm volatile("cp.async.wait_group 0;")

__device__ __forceinline__ void ldsm_x4(uint32_t* r, uint32_t addr) {
    asm volatile("ldmatrix.sync.aligned.m8n8.x4.shared.b16 {%0,%1,%2,%3}, [%4];"
        : "=r"(r[0]), "=r"(r[1]), "=r"(r[2]), "=r"(r[3]) : "r"(addr));
}
__device__ __forceinline__ void mma_fp16(float* c, const uint32_t* a, const uint32_t* b) {
    asm volatile("mma.sync.aligned.m16n8k16.row.col.f32.f16.f16.f32 "
        "{%0,%1,%2,%3}, {%4,%5,%6,%7}, {%8,%9}, {%0,%1,%2,%3};"
        : "+f"(c[0]), "+f"(c[1]), "+f"(c[2]), "+f"(c[3])
        : "r"(a[0]), "r"(a[1]), "r"(a[2]), "r"(a[3]), "r"(b[0]), "r"(b[1]));
}
// 128B-row swizzle: 16B chunk c (0..7) of row r
__device__ __forceinline__ uint32_t sw128(int r, int c) {
    return (uint32_t)(r*128 + ((c ^ (r & 7)) << 4));
}
__device__ __forceinline__ float sigmoidf_(float x) { return 1.0f / (1.0f + expf(-x)); }

// ---------------- kernel 1: gathers + qWh = emb_ctxt[idx] @ W_h + attn_b ----
__global__ void setup_kernel(const int* __restrict__ fc, const int* __restrict__ ft,
                             const float* __restrict__ emb_c, const float* __restrict__ emb_t,
                             const float* __restrict__ attn_W, const float* __restrict__ attn_b)
{
    __shared__ float q[HH];
    int b = blockIdx.x, tid = threadIdx.x;
    int ci = fc[b], ti = ft[b];
    q[tid] = emb_c[ci*HH + tid];
    g_embT[b*HH + tid] = emb_t[ti*HH + tid];
    __syncthreads();
    float acc = attn_b[tid];
#pragma unroll 8
    for (int k = 0; k < HH; k++) acc += q[k] * attn_W[k*HH + tid];
    g_qWh[b*HH + tid] = acc;
}

// ---------------- kernel 1b: W_e transpose + fp16 convert ----------------
__global__ void prep_W(const float* __restrict__ attn_W)
{
    const float* We = attn_W + HH*HH;                  // [k=512][n=256]
    int idx = blockIdx.x * 256 + threadIdx.x;          // 131072
    int k = idx >> 8, n = idx & 255;
    g_Wh[n*FF + k] = __float2half_rn(We[k*HH + n]);
}

// ---------------- kernel 2: fp16 mma.sync scores GEMM (occupancy 2) -------
// Per CTA: 64 s-rows x 256 h-cols x K=512.  256 threads, 8 warps (2m x 4n),
// warp tile 32x64. Single fp16 MMA per product, fp32 accum.
// K pipelined in 8 chunks of 64, double-buffered; 2 CTAs/SM so one CTA's
// producer/sync/epilogue overlaps the other's MMA phase.
#define STAGE   40960                // A 8KB + B 32KB
#define A_OFF   0
#define B_OFF   8192
#define SM_QW   (2*STAGE)
#define SM_V    (SM_QW + 1024)
#define SM_RED  (SM_V + 1024)
#define SMEM_SC (SM_RED + 1024)

__global__ void __launch_bounds__(256, 2)
scores_mma(const float* __restrict__ E, const float* __restrict__ v)
{
    extern __shared__ char sm[];
    const uint32_t smb = smem_u32(sm);
    const int tid  = threadIdx.x;
    const int lane = tid & 31, warp = tid >> 5;
    const int wm = warp >> 2, wn = warp & 3;       // 2 x 4 warp grid
    const int s0 = blockIdx.x * 64;
    const int b  = blockIdx.y;

    float* sq = (float*)(sm + SM_QW);
    float* sv = (float*)(sm + SM_V);
    sq[tid] = g_qWh[b*HH + tid];
    sv[tid] = v[tid];

    // A producer mapping: row0 = tid>>2 (0..63), seg = tid&3 (16 k each)
    const int seg  = tid & 3;
    const int row0 = tid >> 2;
    const float* Ap = E + ((long)(b*SS + s0 + row0))*FF + seg*16;
    const uint32_t dA0 = sw128(row0, seg*2);
    const uint32_t dA1 = sw128(row0, seg*2 + 1);

    float acc[2][8][4];
#pragma unroll
    for (int mt = 0; mt < 2; mt++)
#pragma unroll
        for (int nt = 0; nt < 8; nt++)
#pragma unroll
            for (int e = 0; e < 4; e++) acc[mt][nt][e] = 0.0f;

    // issue cp.async for B chunk (into stage pointer stp)
#define B_FETCH(stp, k0)                                                         \
    do {                                                                         \
        _Pragma("unroll")                                                        \
        for (int j = 0; j < 8; j++) {                                            \
            int idx = tid + 256*j;                                               \
            int br = idx >> 3, bc = idx & 7;                                     \
            cp_async16((stp) + B_OFF + sw128(br, bc),                            \
                       g_Wh + (long)br*FF + (k0) + bc*8);                        \
        }                                                                        \
        CP_COMMIT();                                                             \
    } while (0)

    // convert 16 prefetched floats -> fp16 and store to stage
#define A_STORE(stp, f0, f1, f2, f3)                                             \
    do {                                                                         \
        __half2 h0 = __floats2half2_rn((f0).x, (f0).y);                          \
        __half2 h1 = __floats2half2_rn((f0).z, (f0).w);                          \
        __half2 h2 = __floats2half2_rn((f1).x, (f1).y);                          \
        __half2 h3 = __floats2half2_rn((f1).z, (f1).w);                          \
        __half2 h4 = __floats2half2_rn((f2).x, (f2).y);                          \
        __half2 h5 = __floats2half2_rn((f2).z, (f2).w);                          \
        __half2 h6 = __floats2half2_rn((f3).x, (f3).y);                          \
        __half2 h7 = __floats2half2_rn((f3).z, (f3).w);                          \
        *(uint4*)((stp) + A_OFF + dA0) = make_uint4(                             \
            *(uint32_t*)&h0, *(uint32_t*)&h1, *(uint32_t*)&h2, *(uint32_t*)&h3); \
        *(uint4*)((stp) + A_OFF + dA1) = make_uint4(                             \
            *(uint32_t*)&h4, *(uint32_t*)&h5, *(uint32_t*)&h6, *(uint32_t*)&h7); \
    } while (0)

    // ---- prologue: chunk 0 into stage 0 ----
    {
        B_FETCH(sm, 0);
        float4 f0 = *(const float4*)(Ap);
        float4 f1 = *(const float4*)(Ap + 4);
        float4 f2 = *(const float4*)(Ap + 8);
        float4 f3 = *(const float4*)(Ap + 12);
        A_STORE(sm, f0, f1, f2, f3);
        CP_WAIT0();
        __syncthreads();
    }

    for (int c = 0; c < 8; c++) {
        const int cur = c & 1;
        char* stn = sm + (cur ^ 1)*STAGE;
        const uint32_t stcb = smb + cur*STAGE;

        // ---- prefetch chunk c+1: cp.async B + LDG A into registers ----
        float4 f0, f1, f2, f3;
        if (c < 7) {
            const int k1 = (c + 1)*64;
            B_FETCH(stn, k1);
            f0 = *(const float4*)(Ap + k1);
            f1 = *(const float4*)(Ap + k1 + 4);
            f2 = *(const float4*)(Ap + k1 + 8);
            f3 = *(const float4*)(Ap + k1 + 12);
        }

        // ---- MMAs on stage cur (4 k16-steps) — covers LDG latency ----
#pragma unroll
        for (int ks = 0; ks < 4; ks++) {
            uint32_t af[2][4];
#pragma unroll
            for (int mt = 0; mt < 2; mt++) {
                int r = wm*32 + mt*16 + (lane & 15);
                ldsm_x4(af[mt], stcb + A_OFF + sw128(r, ks*2 + (lane >> 4)));
            }
#pragma unroll
            for (int nb = 0; nb < 4; nb++) {
                int nr = wn*64 + nb*16 + ((lane >> 4) << 3) + (lane & 7);
                int cc = ks*2 + ((lane >> 3) & 1);
                uint32_t r4[4];
                ldsm_x4(r4, stcb + B_OFF + sw128(nr, cc));
                uint32_t b0[2] = { r4[0], r4[1] };
                uint32_t b1[2] = { r4[2], r4[3] };
#pragma unroll
                for (int mt = 0; mt < 2; mt++) {
                    mma_fp16(acc[mt][nb*2],     af[mt], b0);
                    mma_fp16(acc[mt][nb*2 + 1], af[mt], b1);
                }
            }
        }

        // ---- convert + STS chunk c+1 after MMAs ----
        if (c < 7) {
            A_STORE(stn, f0, f1, f2, f3);
            CP_WAIT0();
        }
        __syncthreads();
    }

    // ---- epilogue: +qWh, tanh, dot v over full N=256 ----
    float* red = (float*)(sm + SM_RED);   // [64 rows][4 n-warp groups]
#pragma unroll
    for (int mt = 0; mt < 2; mt++) {
        float pA = 0.0f, pB = 0.0f;
#pragma unroll
        for (int nt = 0; nt < 8; nt++) {
            int h0 = wn*64 + nt*8 + (lane & 3)*2;
            float q0 = sq[h0], q1 = sq[h0 + 1];
            float v0 = sv[h0], v1 = sv[h0 + 1];
            pA += v0*tanhf(acc[mt][nt][0] + q0) + v1*tanhf(acc[mt][nt][1] + q1);
            pB += v0*tanhf(acc[mt][nt][2] + q0) + v1*tanhf(acc[mt][nt][3] + q1);
        }
        pA += __shfl_xor_sync(0xffffffffu, pA, 1);
        pA += __shfl_xor_sync(0xffffffffu, pA, 2);
        pB += __shfl_xor_sync(0xffffffffu, pB, 1);
        pB += __shfl_xor_sync(0xffffffffu, pB, 2);
        if ((lane & 3) == 0) {
            int r = wm*32 + mt*16 + (lane >> 2);
            red[r*4 + wn]       = pA;
            red[(r + 8)*4 + wn] = pB;
        }
    }
    __syncthreads();
    if (tid < 64) {
        float s = red[tid*4] + red[tid*4+1] + red[tid*4+2] + red[tid*4+3];
        g_spart[(long)b*SS + s0 + tid] = s;
    }
}

// ---------------- kernel 3: softmax -> g_scores ----------------
__global__ void softmax_kernel()
{
    __shared__ float red[32];
    const int b = blockIdx.x, tid = threadIdx.x;
    float4 xv = *(const float4*)(g_spart + (long)b*SS + tid*4);
    const unsigned lane = tid & 31, w = tid >> 5;

    float mx = fmaxf(fmaxf(xv.x, xv.y), fmaxf(xv.z, xv.w));
#pragma unroll
    for (int o = 16; o; o >>= 1) mx = fmaxf(mx, __shfl_xor_sync(0xffffffffu, mx, o));
    if (!lane) red[w] = mx;
    __syncthreads();
    if (tid < 32) {
        float t = red[tid];
#pragma unroll
        for (int o = 16; o; o >>= 1) t = fmaxf(t, __shfl_xor_sync(0xffffffffu, t, o));
        if (!tid) red[0] = t;
    }
    __syncthreads();
    const float mm = red[0];
    __syncthreads();

    float4 ev = make_float4(expf(xv.x - mm), expf(xv.y - mm),
                            expf(xv.z - mm), expf(xv.w - mm));
    float s = ev.x + ev.y + ev.z + ev.w;
#pragma unroll
    for (int o = 16; o; o >>= 1) s += __shfl_xor_sync(0xffffffffu, s, o);
    if (!lane) red[w] = s;
    __syncthreads();
    if (tid < 32) {
        float t = red[tid];
#pragma unroll
        for (int o = 16; o; o >>= 1) t += __shfl_xor_sync(0xffffffffu, t, o);
        if (!tid) red[0] = t;
    }
    __syncthreads();
    const float inv = 1.0f / red[0];
    ev.x *= inv; ev.y *= inv; ev.z *= inv; ev.w *= inv;
    *(float4*)(g_scores + b*SS + tid*4) = ev;
}

// ---------------- kernel 4: context partials: part[c][b][f] ----------------
__global__ void ctx_kernel(const float* __restrict__ E)
{
    __shared__ float sa[SS / NCHUNK];
    const int c = blockIdx.x, b = blockIdx.y, tid = threadIdx.x; // 128 threads
    const int s0 = c * (SS / NCHUNK);
    sa[tid]       = g_scores[b*SS + s0 + tid];
    sa[tid + 128] = g_scores[b*SS + s0 + tid + 128];
    __syncthreads();

    float4 acc = make_float4(0.f, 0.f, 0.f, 0.f);
    const float* base = E + (long)(b*SS + s0) * FF + tid*4;
#pragma unroll 8
    for (int s = 0; s < SS / NCHUNK; s++) {
        const float a = sa[s];
        const float4 e = *(const float4*)(base + (long)s * FF);
        acc.x += a*e.x; acc.y += a*e.y; acc.z += a*e.z; acc.w += a*e.w;
    }
    *(float4*)(&g_part[(long)(c*BB + b)*FF + tid*4]) = acc;
}

// ---------------- kernel 5: reduce + GRU + output projection ----------------
__global__ void gru_kernel(const float* __restrict__ w_ih, const float* __restrict__ b_ih,
                           const float* __restrict__ b_hh, const float* __restrict__ out_W,
                           const float* __restrict__ out_b, float* __restrict__ out,
                           int out_size)
{
    __shared__ float x[3*HH];
    __shared__ float g[3*HH];
    __shared__ float h[HH];
    const int b = blockIdx.x, tid = threadIdx.x; // 256 threads

#pragma unroll
    for (int r = 0; r < 2; r++) {
        const int f = tid + r*256;
        float acc = 0.0f;
#pragma unroll
        for (int c = 0; c < NCHUNK; c++) acc += g_part[(long)(c*BB + b)*FF + f];
        x[HH + f] = acc;
    }
    x[tid] = g_embT[b*HH + tid];
    __syncthreads();

#pragma unroll
    for (int r = 0; r < 3; r++) {
        const int jj = tid + r*256;
        float acc = b_ih[jj];
#pragma unroll 8
        for (int k = 0; k < 3*HH; k++) acc += x[k] * w_ih[k*(3*HH) + jj];
        g[jj] = acc;
    }
    __syncthreads();

    {
        const int j = tid;
        const float rg = sigmoidf_(g[j]        + b_hh[j]);
        const float zg = sigmoidf_(g[HH + j]   + b_hh[HH + j]);
        const float ng = tanhf   (g[2*HH + j]  + rg * b_hh[2*HH + j]);
        const float hv = (1.0f - zg) * ng;
        h[j] = hv;
        const int ho = BB*OUTD + b*HH + j;
        if (ho < out_size) out[ho] = hv;
    }
    __syncthreads();

    if (tid < OUTD) {
        float acc = out_b[tid];
#pragma unroll 8
        for (int k = 0; k < HH; k++) acc += h[k] * out_W[k*OUTD + tid];
        out[b*OUTD + tid] = acc;
    }
}

// ---------------- launch ----------------
extern "C" void kernel_launch(void* const* d_in, const int* in_sizes, int n_in,
                              void* d_out, int out_size)
{
    const int*   fc     = (const int*)  d_in[0];   // fut_ctxt (B,1)
    const int*   ft     = (const int*)  d_in[1];   // fut_temp (B,1)
    const float* E      = (const float*)d_in[2];   // encoder_outputs (B,S,2H)
    const float* emb_c  = (const float*)d_in[3];   // emb_ctxt (1000,H)
    const float* emb_t  = (const float*)d_in[4];   // emb_temp (1000,H)
    const float* attn_W = (const float*)d_in[5];   // (3H,H)
    const float* attn_b = (const float*)d_in[6];   // (H,)
    const float* v      = (const float*)d_in[7];   // (H,)
    const float* w_ih   = (const float*)d_in[8];   // (3H,3H)
    // d_in[9] = w_hh: unused since h0 == 0 (gh = b_hh exactly)
    const float* b_ih   = (const float*)d_in[10];  // (3H,)
    const float* b_hh   = (const float*)d_in[11];  // (3H,)
    const float* out_W  = (const float*)d_in[12];  // (H,OUT)
    const float* out_b  = (const float*)d_in[13];  // (OUT,)
    float* out = (float*)d_out;

    cudaFuncSetAttribute(scores_mma, cudaFuncAttributeMaxDynamicSharedMemorySize,
                         SMEM_SC);

    setup_kernel<<<BB, HH>>>(fc, ft, emb_c, emb_t, attn_W, attn_b);
    prep_W<<<512, 256>>>(attn_W);
    scores_mma<<<dim3(SS/64, BB), 256, SMEM_SC>>>(E, v);
    softmax_kernel<<<BB, 1024>>>();
    ctx_kernel<<<dim3(NCHUNK, BB), 128>>>(E);
    gru_kernel<<<BB, 256>>>(w_ih, b_ih, b_hh, out_W, out_b, out, out_size);
}